// round 1
// baseline (speedup 1.0000x reference)
#include <cuda_runtime.h>
#include <cuda_bf16.h>
#include <math.h>

// Problem constants
#define BB 2
#define PP 4096
#define HID 1152
#define NH 16
#define HD 72
#define MTOT (BB*PP)            // 8192

// ---------------- scratch (device globals; no allocations allowed) ----------
__device__ float g_q[(size_t)MTOT * HID];
__device__ float g_k[(size_t)MTOT * HID];
__device__ float g_v[(size_t)MTOT * HID];
__device__ float g_o[(size_t)MTOT * HID];

// ---------------- SGEMM: C[M,N] = A[M,K] @ B[K,N], fp32, 128x128x8 ----------
__global__ __launch_bounds__(256, 2)
void sgemm_kernel(const float* __restrict__ A, const float* __restrict__ B,
                  float* __restrict__ C, int M, int N, int K)
{
    const int BM = 128, BN = 128, BK = 8, TM = 8, TN = 8;
    __shared__ float As[BK][BM];
    __shared__ float Bs[BK][BN];

    int tid = threadIdx.x;
    int tx = tid & 15;           // 16 col groups
    int ty = tid >> 4;           // 16 row groups
    int row0 = blockIdx.y * BM;
    int col0 = blockIdx.x * BN;

    float acc[TM][TN];
#pragma unroll
    for (int m = 0; m < TM; m++)
#pragma unroll
        for (int n = 0; n < TN; n++) acc[m][n] = 0.f;

    int arow = tid >> 1;               // 0..127
    int acol = (tid & 1) * 4;          // 0 or 4
    int brow = tid >> 5;               // 0..7
    int bcol = (tid & 31) * 4;         // 0..124

    for (int k0 = 0; k0 < K; k0 += BK) {
        float4 av = *(const float4*)(A + (size_t)(row0 + arow) * K + k0 + acol);
        As[acol + 0][arow] = av.x;
        As[acol + 1][arow] = av.y;
        As[acol + 2][arow] = av.z;
        As[acol + 3][arow] = av.w;
        *(float4*)(&Bs[brow][bcol]) =
            *(const float4*)(B + (size_t)(k0 + brow) * N + col0 + bcol);
        __syncthreads();

#pragma unroll
        for (int kk = 0; kk < BK; kk++) {
            float a[TM], b[TN];
#pragma unroll
            for (int m = 0; m < TM; m++) a[m] = As[kk][ty * TM + m];
#pragma unroll
            for (int n = 0; n < TN; n++) b[n] = Bs[kk][tx * TN + n];
#pragma unroll
            for (int m = 0; m < TM; m++)
#pragma unroll
                for (int n = 0; n < TN; n++) acc[m][n] = fmaf(a[m], b[n], acc[m][n]);
        }
        __syncthreads();
    }

#pragma unroll
    for (int m = 0; m < TM; m++) {
        float* crow = C + (size_t)(row0 + ty * TM + m) * N + col0 + tx * TN;
        float4 v0 = make_float4(acc[m][0], acc[m][1], acc[m][2], acc[m][3]);
        float4 v1 = make_float4(acc[m][4], acc[m][5], acc[m][6], acc[m][7]);
        *(float4*)(crow) = v0;
        *(float4*)(crow + 4) = v1;
    }
}

// ------------- fused RMSNorm (+weight) + 2D RoPE; one warp per head ---------
// q,k: norm*w then rope; v: norm only.
__global__ void norm_rope_kernel(float* __restrict__ q, float* __restrict__ k,
                                 float* __restrict__ v,
                                 const float* __restrict__ cosb,
                                 const float* __restrict__ sinb,
                                 const float* __restrict__ qw,
                                 const float* __restrict__ kw)
{
    __shared__ float sm[8][HD];
    int warp = threadIdx.x >> 5;
    int lane = threadIdx.x & 31;
    int gid = blockIdx.x * 8 + warp;     // 0 .. B*P*NH-1
    int bp = gid >> 4;
    int h  = gid & 15;
    size_t base  = (size_t)bp * HID + (size_t)h * HD;
    size_t cbase = (size_t)bp * HD;

    float c0 = cosb[cbase + lane],      s0 = sinb[cbase + lane];
    float c1 = cosb[cbase + 32 + lane], s1 = sinb[cbase + 32 + lane];
    float c2 = 0.f, s2 = 0.f;
    if (lane < 8) { c2 = cosb[cbase + 64 + lane]; s2 = sinb[cbase + 64 + lane]; }

#pragma unroll
    for (int t = 0; t < 2; t++) {
        float* buf = (t == 0) ? q : k;
        const float* w = (t == 0) ? qw : kw;
        float x0 = buf[base + lane];
        float x1 = buf[base + 32 + lane];
        float x2 = (lane < 8) ? buf[base + 64 + lane] : 0.f;
        float ss = x0 * x0 + x1 * x1 + x2 * x2;
#pragma unroll
        for (int m = 16; m; m >>= 1) ss += __shfl_xor_sync(0xffffffffu, ss, m);
        float r = rsqrtf(ss * (1.0f / 72.0f) + 1e-6f);
        sm[warp][lane]      = x0 * r * w[lane];
        sm[warp][lane + 32] = x1 * r * w[lane + 32];
        if (lane < 8) sm[warp][lane + 64] = x2 * r * w[lane + 64];
        __syncwarp();
        // rope on d = lane, lane+32, (lane<8) lane+64
        {
            int d = lane;
            int jj = (d < 36) ? d : d - 36;
            float rh = (jj < 18) ? -sm[warp][d + 18] : sm[warp][d - 18];
            buf[base + d] = sm[warp][d] * c0 + rh * s0;
        }
        {
            int d = lane + 32;
            int jj = (d < 36) ? d : d - 36;
            float rh = (jj < 18) ? -sm[warp][d + 18] : sm[warp][d - 18];
            buf[base + d] = sm[warp][d] * c1 + rh * s1;
        }
        if (lane < 8) {
            int d = lane + 64;
            int jj = d - 36;
            float rh = (jj < 18) ? -sm[warp][d + 18] : sm[warp][d - 18];
            buf[base + d] = sm[warp][d] * c2 + rh * s2;
        }
        __syncwarp();
    }
    // v: rms norm only
    {
        float x0 = v[base + lane];
        float x1 = v[base + 32 + lane];
        float x2 = (lane < 8) ? v[base + 64 + lane] : 0.f;
        float ss = x0 * x0 + x1 * x1 + x2 * x2;
#pragma unroll
        for (int m = 16; m; m >>= 1) ss += __shfl_xor_sync(0xffffffffu, ss, m);
        float r = rsqrtf(ss * (1.0f / 72.0f) + 1e-6f);
        v[base + lane]      = x0 * r;
        v[base + 32 + lane] = x1 * r;
        if (lane < 8) v[base + 64 + lane] = x2 * r;
    }
}

// ---------------- flash attention: 64x64 tiles, online softmax --------------
// Layouts in smem:
//   Qs: [72][65]  (transposed: d-major), Ks: [72][65] (transposed)
//   Vs: [64][80]  (row-major),           Ss: [64][65] (P tile)
#define QK_STRIDE 65
#define V_STRIDE 80
#define S_STRIDE 65
#define ATTN_SMEM_FLOATS (72*QK_STRIDE*2 + 64*V_STRIDE + 64*S_STRIDE)

__global__ __launch_bounds__(256, 2)
void attn_kernel(const float* __restrict__ q, const float* __restrict__ k,
                 const float* __restrict__ v, float* __restrict__ o)
{
    extern __shared__ float smem[];
    float* Qs = smem;
    float* Ks = Qs + 72 * QK_STRIDE;
    float* Vs = Ks + 72 * QK_STRIDE;
    float* Ss = Vs + 64 * V_STRIDE;

    int tid = threadIdx.x;
    int tx = tid & 15;
    int ty = tid >> 4;
    int q0 = blockIdx.x * 64;
    int h  = blockIdx.y;
    int b  = blockIdx.z;
    size_t bbase = (size_t)b * PP * HID + (size_t)h * HD;

    // load Q tile transposed
    for (int i = tid; i < 64 * 72; i += 256) {
        int d = i % 72, r = i / 72;
        Qs[d * QK_STRIDE + r] = q[bbase + (size_t)(q0 + r) * HID + d];
    }

    float m[4], l[4], accO[4][5];
#pragma unroll
    for (int i = 0; i < 4; i++) {
        m[i] = -1e30f; l[i] = 0.f;
#pragma unroll
        for (int j = 0; j < 5; j++) accO[i][j] = 0.f;
    }
    __syncthreads();

    for (int kt = 0; kt < PP; kt += 64) {
        // load K (transposed) + V (row major)
        for (int i = tid; i < 64 * 72; i += 256) {
            int d = i % 72, r = i / 72;
            size_t g = bbase + (size_t)(kt + r) * HID + d;
            Ks[d * QK_STRIDE + r] = k[g];
            Vs[r * V_STRIDE + d]  = v[g];
        }
        __syncthreads();

        // S = Q K^T (64x64), 4x4 per thread
        float acc[4][4];
#pragma unroll
        for (int i = 0; i < 4; i++)
#pragma unroll
            for (int j = 0; j < 4; j++) acc[i][j] = 0.f;

        for (int d = 0; d < 72; d++) {
            float a[4], bb[4];
#pragma unroll
            for (int i = 0; i < 4; i++) a[i]  = Qs[d * QK_STRIDE + ty * 4 + i];
#pragma unroll
            for (int j = 0; j < 4; j++) bb[j] = Ks[d * QK_STRIDE + tx * 4 + j];
#pragma unroll
            for (int i = 0; i < 4; i++)
#pragma unroll
                for (int j = 0; j < 4; j++) acc[i][j] = fmaf(a[i], bb[j], acc[i][j]);
        }

        // online softmax (rows owned by 16 tx-threads; reduce across tx group)
#pragma unroll
        for (int i = 0; i < 4; i++) {
            float mx = fmaxf(fmaxf(acc[i][0], acc[i][1]), fmaxf(acc[i][2], acc[i][3]));
#pragma unroll
            for (int msk = 8; msk; msk >>= 1)
                mx = fmaxf(mx, __shfl_xor_sync(0xffffffffu, mx, msk));
            float mn = fmaxf(m[i], mx);
            float alpha = __expf(m[i] - mn);
            m[i] = mn;
            float rs = 0.f;
#pragma unroll
            for (int j = 0; j < 4; j++) {
                float p = __expf(acc[i][j] - mn);
                Ss[(ty * 4 + i) * S_STRIDE + tx * 4 + j] = p;
                rs += p;
            }
#pragma unroll
            for (int msk = 8; msk; msk >>= 1)
                rs += __shfl_xor_sync(0xffffffffu, rs, msk);
            l[i] = l[i] * alpha + rs;
#pragma unroll
            for (int j = 0; j < 5; j++) accO[i][j] *= alpha;
        }
        __syncthreads();

        // O += P @ V   (rows ty*4+i, cols tx*5+j of 72, padded to 80)
        for (int kk = 0; kk < 64; kk++) {
            float p[4], vv[5];
#pragma unroll
            for (int i = 0; i < 4; i++) p[i]  = Ss[(ty * 4 + i) * S_STRIDE + kk];
#pragma unroll
            for (int j = 0; j < 5; j++) vv[j] = Vs[kk * V_STRIDE + tx * 5 + j];
#pragma unroll
            for (int i = 0; i < 4; i++)
#pragma unroll
                for (int j = 0; j < 5; j++) accO[i][j] = fmaf(p[i], vv[j], accO[i][j]);
        }
        __syncthreads();
    }

    // epilogue
#pragma unroll
    for (int i = 0; i < 4; i++) {
        float inv = 1.0f / l[i];
        int r = ty * 4 + i;
#pragma unroll
        for (int j = 0; j < 5; j++) {
            int d = tx * 5 + j;
            if (d < 72)
                o[bbase + (size_t)(q0 + r) * HID + d] = accO[i][j] * inv;
        }
    }
}

// ---------------------------------- launch ----------------------------------
extern "C" void kernel_launch(void* const* d_in, const int* in_sizes, int n_in,
                              void* d_out, int out_size)
{
    const float* hidden = (const float*)d_in[0];
    const float* cosb   = (const float*)d_in[1];
    const float* sinb   = (const float*)d_in[2];
    const float* Wq     = (const float*)d_in[3];
    const float* Wk     = (const float*)d_in[4];
    const float* Wv     = (const float*)d_in[5];
    const float* Wo     = (const float*)d_in[6];
    const float* qw     = (const float*)d_in[7];
    const float* kw     = (const float*)d_in[8];
    float* out = (float*)d_out;

    float *q, *k, *v, *o;
    cudaGetSymbolAddress((void**)&q, g_q);
    cudaGetSymbolAddress((void**)&k, g_k);
    cudaGetSymbolAddress((void**)&v, g_v);
    cudaGetSymbolAddress((void**)&o, g_o);

    size_t attn_smem = (size_t)ATTN_SMEM_FLOATS * sizeof(float);
    cudaFuncSetAttribute(attn_kernel, cudaFuncAttributeMaxDynamicSharedMemorySize,
                         (int)attn_smem);

    dim3 ggrid(HID / 128, MTOT / 128);   // (9, 64)
    sgemm_kernel<<<ggrid, 256>>>(hidden, Wq, q, MTOT, HID, HID);
    sgemm_kernel<<<ggrid, 256>>>(hidden, Wk, k, MTOT, HID, HID);
    sgemm_kernel<<<ggrid, 256>>>(hidden, Wv, v, MTOT, HID, HID);

    norm_rope_kernel<<<(BB * PP * NH) / 8, 256>>>(q, k, v, cosb, sinb, qw, kw);

    dim3 agrid(PP / 64, NH, BB);         // (64, 16, 2)
    attn_kernel<<<agrid, 256, attn_smem>>>(q, k, v, o);

    sgemm_kernel<<<ggrid, 256>>>(o, Wo, out, MTOT, HID, HID);
}

// round 3
// speedup vs baseline: 1.6931x; 1.6931x over previous
#include <cuda_runtime.h>
#include <cuda_bf16.h>
#include <math.h>
#include <stdint.h>

#define BB 2
#define PP 4096
#define HID 1152
#define NH 16
#define HD 72
#define MTOT (BB*PP)            // 8192

// ---------------- scratch (device globals; no allocations allowed) ----------
__device__ float g_q[(size_t)MTOT * HID];
__device__ float g_k[(size_t)MTOT * HID];
__device__ float g_v[(size_t)MTOT * HID];
__device__ float g_o[(size_t)MTOT * HID];
__device__ __nv_bfloat16 g_qh[(size_t)MTOT * HID];
__device__ __nv_bfloat16 g_ql[(size_t)MTOT * HID];
__device__ __nv_bfloat16 g_kh[(size_t)MTOT * HID];
__device__ __nv_bfloat16 g_kl[(size_t)MTOT * HID];
__device__ __nv_bfloat16 g_vh[(size_t)MTOT * HID];
__device__ __nv_bfloat16 g_vl[(size_t)MTOT * HID];

// ---------------- mma.sync helpers ------------------------------------------
__device__ __forceinline__ void mma16816(float* c, const uint32_t* a, const uint32_t* b) {
    asm volatile(
        "mma.sync.aligned.m16n8k16.row.col.f32.bf16.bf16.f32 "
        "{%0,%1,%2,%3}, {%4,%5,%6,%7}, {%8,%9}, {%0,%1,%2,%3};"
        : "+f"(c[0]), "+f"(c[1]), "+f"(c[2]), "+f"(c[3])
        : "r"(a[0]), "r"(a[1]), "r"(a[2]), "r"(a[3]), "r"(b[0]), "r"(b[1]));
}

// split two fp32 into packed bf16 hi / lo residual pairs (low 16 bits = x0)
__device__ __forceinline__ void split2(float x0, float x1, uint32_t& h, uint32_t& l) {
    __nv_bfloat16 h0 = __float2bfloat16_rn(x0);
    __nv_bfloat16 h1 = __float2bfloat16_rn(x1);
    __nv_bfloat162 hv; hv.x = h0; hv.y = h1;
    __nv_bfloat162 lv = __floats2bfloat162_rn(x0 - __bfloat162float(h0),
                                              x1 - __bfloat162float(h1));
    h = *(uint32_t*)&hv;
    l = *(uint32_t*)&lv;
}

__device__ __forceinline__ uint32_t lds32(const __nv_bfloat16* p) {
    return *(const uint32_t*)p;
}

// ============== MMA GEMM: C[M,N=1152] = A[M,K=1152] @ W[K,N], bf16x3 ========
// CTA tile 128x128, K-chunk 32, 8 warps (4m x 2n), warp tile 32x64.
#define ASTR 40   // A smem k-stride (conflict-free for frag loads)

__device__ __forceinline__ void mma_gemm_body(
    const float* __restrict__ A, const float* __restrict__ W,
    float* __restrict__ C, int m0, int n0)
{
    __shared__ __nv_bfloat16 Ah[128][ASTR], Al[128][ASTR];
    __shared__ __nv_bfloat16 Bh[128][ASTR], Bl[128][ASTR];

    const int tid = threadIdx.x;
    const int lane = tid & 31;
    const int wid = tid >> 5;
    const int wm = wid & 3;            // 0..3 -> rows wm*32
    const int wn = wid >> 2;           // 0..1 -> cols wn*64

    float c[2][8][4];
#pragma unroll
    for (int mt = 0; mt < 2; mt++)
#pragma unroll
        for (int nt = 0; nt < 8; nt++)
#pragma unroll
            for (int e = 0; e < 4; e++) c[mt][nt][e] = 0.f;

    const int bn = tid & 127;          // B: n column owned by this thread
    const int bko = (tid >> 7) * 16;   // B: k half

    float4 a4[4];
    float br[16];

    // prefetch chunk 0
    {
        const int k0 = 0;
#pragma unroll
        for (int j = 0; j < 4; j++) {
            int flat = j * 1024 + tid * 4;
            int row = flat >> 5, col = flat & 31;
            a4[j] = *(const float4*)(A + (size_t)(m0 + row) * HID + k0 + col);
        }
#pragma unroll
        for (int e = 0; e < 16; e++)
            br[e] = W[(size_t)(k0 + bko + e) * HID + n0 + bn];
    }

    const int NCH = HID / 32;          // 36
    for (int ch = 0; ch < NCH; ch++) {
        // ---- store prefetched chunk to smem (with hi/lo split) ----
#pragma unroll
        for (int j = 0; j < 4; j++) {
            int flat = j * 1024 + tid * 4;
            int row = flat >> 5, col = flat & 31;
            uint32_t h, l;
            split2(a4[j].x, a4[j].y, h, l);
            *(uint32_t*)&Ah[row][col] = h; *(uint32_t*)&Al[row][col] = l;
            split2(a4[j].z, a4[j].w, h, l);
            *(uint32_t*)&Ah[row][col + 2] = h; *(uint32_t*)&Al[row][col + 2] = l;
        }
#pragma unroll
        for (int e = 0; e < 16; e += 2) {
            uint32_t h, l;
            split2(br[e], br[e + 1], h, l);
            *(uint32_t*)&Bh[bn][bko + e] = h; *(uint32_t*)&Bl[bn][bko + e] = l;
        }
        __syncthreads();

        // ---- prefetch next chunk (overlaps with mma below) ----
        if (ch + 1 < NCH) {
            const int k0 = (ch + 1) * 32;
#pragma unroll
            for (int j = 0; j < 4; j++) {
                int flat = j * 1024 + tid * 4;
                int row = flat >> 5, col = flat & 31;
                a4[j] = *(const float4*)(A + (size_t)(m0 + row) * HID + k0 + col);
            }
#pragma unroll
            for (int e = 0; e < 16; e++)
                br[e] = W[(size_t)(k0 + bko + e) * HID + n0 + bn];
        }

        // ---- mma on smem chunk ----
#pragma unroll
        for (int ks = 0; ks < 2; ks++) {
            const int kk = ks * 16 + (lane & 3) * 2;
            uint32_t fah[2][4], fal[2][4];
#pragma unroll
            for (int mt = 0; mt < 2; mt++) {
                int r0 = wm * 32 + mt * 16 + (lane >> 2);
                int r1 = r0 + 8;
                fah[mt][0] = lds32(&Ah[r0][kk]);     fah[mt][1] = lds32(&Ah[r1][kk]);
                fah[mt][2] = lds32(&Ah[r0][kk + 8]); fah[mt][3] = lds32(&Ah[r1][kk + 8]);
                fal[mt][0] = lds32(&Al[r0][kk]);     fal[mt][1] = lds32(&Al[r1][kk]);
                fal[mt][2] = lds32(&Al[r0][kk + 8]); fal[mt][3] = lds32(&Al[r1][kk + 8]);
            }
#pragma unroll
            for (int nt = 0; nt < 8; nt++) {
                int n = wn * 64 + nt * 8 + (lane >> 2);
                uint32_t fbh[2] = { lds32(&Bh[n][kk]), lds32(&Bh[n][kk + 8]) };
                uint32_t fbl[2] = { lds32(&Bl[n][kk]), lds32(&Bl[n][kk + 8]) };
#pragma unroll
                for (int mt = 0; mt < 2; mt++) {
                    mma16816(c[mt][nt], fah[mt], fbh);
                    mma16816(c[mt][nt], fah[mt], fbl);
                    mma16816(c[mt][nt], fal[mt], fbh);
                }
            }
        }
        __syncthreads();
    }

    // ---- epilogue ----
#pragma unroll
    for (int mt = 0; mt < 2; mt++) {
#pragma unroll
        for (int nt = 0; nt < 8; nt++) {
            int row = m0 + wm * 32 + mt * 16 + (lane >> 2);
            int col = n0 + wn * 64 + nt * 8 + (lane & 3) * 2;
            *(float2*)(C + (size_t)row * HID + col) =
                make_float2(c[mt][nt][0], c[mt][nt][1]);
            *(float2*)(C + (size_t)(row + 8) * HID + col) =
                make_float2(c[mt][nt][2], c[mt][nt][3]);
        }
    }
}

__global__ __launch_bounds__(256)
void mma_gemm_qkv(const float* __restrict__ A,
                  const float* __restrict__ Wq, const float* __restrict__ Wk,
                  const float* __restrict__ Wv,
                  float* __restrict__ q, float* __restrict__ k, float* __restrict__ v)
{
    const float* W = (blockIdx.z == 0) ? Wq : (blockIdx.z == 1) ? Wk : Wv;
    float* C = (blockIdx.z == 0) ? q : (blockIdx.z == 1) ? k : v;
    mma_gemm_body(A, W, C, blockIdx.y * 128, blockIdx.x * 128);
}

__global__ __launch_bounds__(256)
void mma_gemm_o(const float* __restrict__ A, const float* __restrict__ W,
                float* __restrict__ C)
{
    mma_gemm_body(A, W, C, blockIdx.y * 128, blockIdx.x * 128);
}

// ------------- fused RMSNorm (+weight) + 2D RoPE + bf16 hi/lo split ---------
__global__ void norm_rope_split(const float* __restrict__ q, const float* __restrict__ k,
                                const float* __restrict__ v,
                                const float* __restrict__ cosb,
                                const float* __restrict__ sinb,
                                const float* __restrict__ qw,
                                const float* __restrict__ kw,
                                __nv_bfloat16* __restrict__ qh, __nv_bfloat16* __restrict__ ql,
                                __nv_bfloat16* __restrict__ kh, __nv_bfloat16* __restrict__ kl,
                                __nv_bfloat16* __restrict__ vh, __nv_bfloat16* __restrict__ vl)
{
    __shared__ float sm[8][HD];
    int warp = threadIdx.x >> 5;
    int lane = threadIdx.x & 31;
    int gid = blockIdx.x * 8 + warp;
    int bp = gid >> 4;
    int h  = gid & 15;
    size_t base  = (size_t)bp * HID + (size_t)h * HD;
    size_t cbase = (size_t)bp * HD;

    float c0 = cosb[cbase + lane],      s0 = sinb[cbase + lane];
    float c1 = cosb[cbase + 32 + lane], s1 = sinb[cbase + 32 + lane];
    float c2 = 0.f, s2 = 0.f;
    if (lane < 8) { c2 = cosb[cbase + 64 + lane]; s2 = sinb[cbase + 64 + lane]; }

#pragma unroll
    for (int t = 0; t < 2; t++) {
        const float* buf = (t == 0) ? q : k;
        const float* w = (t == 0) ? qw : kw;
        __nv_bfloat16* oh = (t == 0) ? qh : kh;
        __nv_bfloat16* ol = (t == 0) ? ql : kl;
        float x0 = buf[base + lane];
        float x1 = buf[base + 32 + lane];
        float x2 = (lane < 8) ? buf[base + 64 + lane] : 0.f;
        float ss = x0 * x0 + x1 * x1 + x2 * x2;
#pragma unroll
        for (int m = 16; m; m >>= 1) ss += __shfl_xor_sync(0xffffffffu, ss, m);
        float r = rsqrtf(ss * (1.0f / 72.0f) + 1e-6f);
        sm[warp][lane]      = x0 * r * w[lane];
        sm[warp][lane + 32] = x1 * r * w[lane + 32];
        if (lane < 8) sm[warp][lane + 64] = x2 * r * w[lane + 64];
        __syncwarp();
        {
            int d = lane;
            int jj = (d < 36) ? d : d - 36;
            float rh = (jj < 18) ? -sm[warp][d + 18] : sm[warp][d - 18];
            float out = sm[warp][d] * c0 + rh * s0;
            __nv_bfloat16 hh = __float2bfloat16_rn(out);
            oh[base + d] = hh;
            ol[base + d] = __float2bfloat16_rn(out - __bfloat162float(hh));
        }
        {
            int d = lane + 32;
            int jj = (d < 36) ? d : d - 36;
            float rh = (jj < 18) ? -sm[warp][d + 18] : sm[warp][d - 18];
            float out = sm[warp][d] * c1 + rh * s1;
            __nv_bfloat16 hh = __float2bfloat16_rn(out);
            oh[base + d] = hh;
            ol[base + d] = __float2bfloat16_rn(out - __bfloat162float(hh));
        }
        if (lane < 8) {
            int d = lane + 64;
            int jj = d - 36;
            float rh = (jj < 18) ? -sm[warp][d + 18] : sm[warp][d - 18];
            float out = sm[warp][d] * c2 + rh * s2;
            __nv_bfloat16 hh = __float2bfloat16_rn(out);
            oh[base + d] = hh;
            ol[base + d] = __float2bfloat16_rn(out - __bfloat162float(hh));
        }
        __syncwarp();
    }
    {
        float x0 = v[base + lane];
        float x1 = v[base + 32 + lane];
        float x2 = (lane < 8) ? v[base + 64 + lane] : 0.f;
        float ss = x0 * x0 + x1 * x1 + x2 * x2;
#pragma unroll
        for (int m = 16; m; m >>= 1) ss += __shfl_xor_sync(0xffffffffu, ss, m);
        float r = rsqrtf(ss * (1.0f / 72.0f) + 1e-6f);
#pragma unroll
        for (int part = 0; part < 3; part++) {
            int d = lane + part * 32;
            if (d < HD) {
                float out = ((part == 0) ? x0 : (part == 1) ? x1 : x2) * r;
                __nv_bfloat16 hh = __float2bfloat16_rn(out);
                vh[base + d] = hh;
                vl[base + d] = __float2bfloat16_rn(out - __bfloat162float(hh));
            }
        }
    }
}

// ---------------- flash attention with mma.sync bf16x3 ----------------------
// CTA: 128 queries x one head; 8 warps, warp = 16 query rows.
// Key tiles of 64. S = Q K^T via mma (k=80 padded), softmax fp32,
// O += P V via mma (P fragments reuse S fragment layout).
#define KSTR 88   // K smem d-stride
#define VSTR 72   // Vt smem key-stride

__global__ __launch_bounds__(256)
void attn_mma(const __nv_bfloat16* __restrict__ qh, const __nv_bfloat16* __restrict__ ql,
              const __nv_bfloat16* __restrict__ kh, const __nv_bfloat16* __restrict__ kl,
              const __nv_bfloat16* __restrict__ vh, const __nv_bfloat16* __restrict__ vl,
              float* __restrict__ o)
{
    __shared__ __nv_bfloat16 Kh[64][KSTR], Kl[64][KSTR];
    __shared__ __nv_bfloat16 Vth[72][VSTR], Vtl[72][VSTR];

    const int tid = threadIdx.x;
    const int lane = tid & 31;
    const int wid = tid >> 5;
    const int b = blockIdx.z, h = blockIdx.y;
    const int q0 = blockIdx.x * 128;
    const size_t rowbase = (size_t)b * PP;
    const size_t hoff = (size_t)h * HD;

    // zero-pad K smem cols 72..79 (read by k-step 4 fragment reg 1)
    if (tid < 128) {
        int r = tid & 63;
        uint4 z = make_uint4(0, 0, 0, 0);
        if (tid < 64) *(uint4*)&Kh[r][72] = z;
        else          *(uint4*)&Kl[r][72] = z;
    }

    // ---- Q fragments, register resident (hi & lo) ----
    uint32_t qfh[5][4], qfl[5][4];
    {
        int ra = q0 + wid * 16 + (lane >> 2);
        const size_t ga = (rowbase + ra) * HID + hoff;
        const size_t gb = ga + (size_t)8 * HID;
#pragma unroll
        for (int ks = 0; ks < 5; ks++) {
            int kk = ks * 16 + (lane & 3) * 2;
            qfh[ks][0] = lds32(qh + ga + kk);
            qfh[ks][1] = lds32(qh + gb + kk);
            qfl[ks][0] = lds32(ql + ga + kk);
            qfl[ks][1] = lds32(ql + gb + kk);
            if (ks < 4) {
                qfh[ks][2] = lds32(qh + ga + kk + 8);
                qfh[ks][3] = lds32(qh + gb + kk + 8);
                qfl[ks][2] = lds32(ql + ga + kk + 8);
                qfl[ks][3] = lds32(ql + gb + kk + 8);
            } else {
                qfh[ks][2] = qfh[ks][3] = 0u;
                qfl[ks][2] = qfl[ks][3] = 0u;
            }
        }
    }

    float m0 = -1e30f, m1 = -1e30f, l0 = 0.f, l1 = 0.f;
    float oacc[9][4];
#pragma unroll
    for (int dt = 0; dt < 9; dt++)
#pragma unroll
        for (int e = 0; e < 4; e++) oacc[dt][e] = 0.f;

    for (int kt = 0; kt < PP / 64; kt++) {
        __syncthreads();   // previous iteration's reads complete before refill
        const size_t kb = rowbase + kt * 64;

        // fill Kh/Kl (row-major, uint4 = 8 bf16)
        for (int i = tid; i < 1152; i += 256) {
            int arr = i >= 576;
            int f = arr ? i - 576 : i;
            int r = f / 9, cc = f % 9;
            const __nv_bfloat16* src = (arr ? kl : kh) + (kb + r) * HID + hoff + cc * 8;
            uint4 val = *(const uint4*)src;
            if (arr) *(uint4*)&Kl[r][cc * 8] = val;
            else     *(uint4*)&Kh[r][cc * 8] = val;
        }
        // fill Vth/Vtl (transposed)
        for (int i = tid; i < 4608; i += 256) {
            int arr = i >= 2304;
            int f = arr ? i - 2304 : i;
            int r = f / 36, cc = f % 36;
            uint32_t val = *(const uint32_t*)((arr ? vl : vh) + (kb + r) * HID + hoff + cc * 2);
            __nv_bfloat162 v2 = *(__nv_bfloat162*)&val;
            if (arr) { Vtl[cc * 2][r] = v2.x; Vtl[cc * 2 + 1][r] = v2.y; }
            else     { Vth[cc * 2][r] = v2.x; Vth[cc * 2 + 1][r] = v2.y; }
        }
        __syncthreads();

        // ---- S = Q K^T ----
        float s[8][4];
#pragma unroll
        for (int nt = 0; nt < 8; nt++)
#pragma unroll
            for (int e = 0; e < 4; e++) s[nt][e] = 0.f;

#pragma unroll
        for (int ks = 0; ks < 5; ks++) {
            const int kk = ks * 16 + (lane & 3) * 2;
#pragma unroll
            for (int nt = 0; nt < 8; nt++) {
                int key = nt * 8 + (lane >> 2);
                uint32_t fbh[2] = { lds32(&Kh[key][kk]), lds32(&Kh[key][kk + 8]) };
                uint32_t fbl[2] = { lds32(&Kl[key][kk]), lds32(&Kl[key][kk + 8]) };
                mma16816(s[nt], qfh[ks], fbh);
                mma16816(s[nt], qfh[ks], fbl);
                mma16816(s[nt], qfl[ks], fbh);
            }
        }

        // ---- online softmax (rows: lane>>2 and +8) ----
        float mx0 = -1e30f, mx1 = -1e30f;
#pragma unroll
        for (int nt = 0; nt < 8; nt++) {
            mx0 = fmaxf(mx0, fmaxf(s[nt][0], s[nt][1]));
            mx1 = fmaxf(mx1, fmaxf(s[nt][2], s[nt][3]));
        }
        mx0 = fmaxf(mx0, __shfl_xor_sync(0xffffffffu, mx0, 1));
        mx0 = fmaxf(mx0, __shfl_xor_sync(0xffffffffu, mx0, 2));
        mx1 = fmaxf(mx1, __shfl_xor_sync(0xffffffffu, mx1, 1));
        mx1 = fmaxf(mx1, __shfl_xor_sync(0xffffffffu, mx1, 2));
        float nm0 = fmaxf(m0, mx0), nm1 = fmaxf(m1, mx1);
        float a0 = __expf(m0 - nm0), a1 = __expf(m1 - nm1);
        m0 = nm0; m1 = nm1;
        float rs0 = 0.f, rs1 = 0.f;
#pragma unroll
        for (int nt = 0; nt < 8; nt++) {
            s[nt][0] = __expf(s[nt][0] - nm0);
            s[nt][1] = __expf(s[nt][1] - nm0);
            s[nt][2] = __expf(s[nt][2] - nm1);
            s[nt][3] = __expf(s[nt][3] - nm1);
            rs0 += s[nt][0] + s[nt][1];
            rs1 += s[nt][2] + s[nt][3];
        }
        rs0 += __shfl_xor_sync(0xffffffffu, rs0, 1);
        rs0 += __shfl_xor_sync(0xffffffffu, rs0, 2);
        rs1 += __shfl_xor_sync(0xffffffffu, rs1, 1);
        rs1 += __shfl_xor_sync(0xffffffffu, rs1, 2);
        l0 = l0 * a0 + rs0;
        l1 = l1 * a1 + rs1;
#pragma unroll
        for (int dt = 0; dt < 9; dt++) {
            oacc[dt][0] *= a0; oacc[dt][1] *= a0;
            oacc[dt][2] *= a1; oacc[dt][3] *= a1;
        }

        // ---- O += P V ----
#pragma unroll
        for (int pk = 0; pk < 4; pk++) {
            uint32_t aph[4], apl[4];
            split2(s[2 * pk][0],     s[2 * pk][1],     aph[0], apl[0]);
            split2(s[2 * pk][2],     s[2 * pk][3],     aph[1], apl[1]);
            split2(s[2 * pk + 1][0], s[2 * pk + 1][1], aph[2], apl[2]);
            split2(s[2 * pk + 1][2], s[2 * pk + 1][3], aph[3], apl[3]);
            const int k2 = pk * 16 + (lane & 3) * 2;
#pragma unroll
            for (int dt = 0; dt < 9; dt++) {
                int d = dt * 8 + (lane >> 2);
                uint32_t fvh[2] = { lds32(&Vth[d][k2]), lds32(&Vth[d][k2 + 8]) };
                uint32_t fvl[2] = { lds32(&Vtl[d][k2]), lds32(&Vtl[d][k2 + 8]) };
                mma16816(oacc[dt], aph, fvh);
                mma16816(oacc[dt], aph, fvl);
                mma16816(oacc[dt], apl, fvh);
            }
        }
    }

    // ---- epilogue ----
    float il0 = 1.0f / l0, il1 = 1.0f / l1;
    int ra = q0 + wid * 16 + (lane >> 2);
#pragma unroll
    for (int dt = 0; dt < 9; dt++) {
        int col = dt * 8 + (lane & 3) * 2;
        *(float2*)(o + (rowbase + ra) * HID + hoff + col) =
            make_float2(oacc[dt][0] * il0, oacc[dt][1] * il0);
        *(float2*)(o + (rowbase + ra + 8) * HID + hoff + col) =
            make_float2(oacc[dt][2] * il1, oacc[dt][3] * il1);
    }
}

// ---------------------------------- launch ----------------------------------
extern "C" void kernel_launch(void* const* d_in, const int* in_sizes, int n_in,
                              void* d_out, int out_size)
{
    const float* hidden = (const float*)d_in[0];
    const float* cosb   = (const float*)d_in[1];
    const float* sinb   = (const float*)d_in[2];
    const float* Wq     = (const float*)d_in[3];
    const float* Wk     = (const float*)d_in[4];
    const float* Wv     = (const float*)d_in[5];
    const float* Wo     = (const float*)d_in[6];
    const float* qw     = (const float*)d_in[7];
    const float* kw     = (const float*)d_in[8];
    float* out = (float*)d_out;

    float *q, *k, *v, *o;
    __nv_bfloat16 *qh, *ql, *kh, *kl, *vh, *vl;
    cudaGetSymbolAddress((void**)&q, g_q);
    cudaGetSymbolAddress((void**)&k, g_k);
    cudaGetSymbolAddress((void**)&v, g_v);
    cudaGetSymbolAddress((void**)&o, g_o);
    cudaGetSymbolAddress((void**)&qh, g_qh);
    cudaGetSymbolAddress((void**)&ql, g_ql);
    cudaGetSymbolAddress((void**)&kh, g_kh);
    cudaGetSymbolAddress((void**)&kl, g_kl);
    cudaGetSymbolAddress((void**)&vh, g_vh);
    cudaGetSymbolAddress((void**)&vl, g_vl);

    dim3 qkvgrid(HID / 128, MTOT / 128, 3);     // (9, 64, 3)
    mma_gemm_qkv<<<qkvgrid, 256>>>(hidden, Wq, Wk, Wv, q, k, v);

    norm_rope_split<<<(BB * PP * NH) / 8, 256>>>(q, k, v, cosb, sinb, qw, kw,
                                                 qh, ql, kh, kl, vh, vl);

    dim3 agrid(PP / 128, NH, BB);               // (32, 16, 2)
    attn_mma<<<agrid, 256>>>(qh, ql, kh, kl, vh, vl, o);

    dim3 ogrid(HID / 128, MTOT / 128);          // (9, 64)
    mma_gemm_o<<<ogrid, 256>>>(o, Wo, out);
}

// round 4
// speedup vs baseline: 3.4328x; 2.0276x over previous
#include <cuda_runtime.h>
#include <cuda_bf16.h>
#include <math.h>
#include <stdint.h>

#define BB 2
#define PP 4096
#define HID 1152
#define NH 16
#define HD 72
#define MTOT (BB*PP)            // 8192

// ---------------- scratch (device globals; no allocations allowed) ----------
__device__ float g_q[(size_t)MTOT * HID];
__device__ float g_k[(size_t)MTOT * HID];
__device__ float g_v[(size_t)MTOT * HID];
__device__ float g_o[(size_t)MTOT * HID];
__device__ __nv_bfloat16 g_hh[(size_t)MTOT * HID];   // hidden hi (reused for o hi)
__device__ __nv_bfloat16 g_hl[(size_t)MTOT * HID];   // hidden lo (reused for o lo)
__device__ __nv_bfloat16 g_qh[(size_t)MTOT * HID];
__device__ __nv_bfloat16 g_ql[(size_t)MTOT * HID];
__device__ __nv_bfloat16 g_kh[(size_t)MTOT * HID];
__device__ __nv_bfloat16 g_kl[(size_t)MTOT * HID];
__device__ __nv_bfloat16 g_vh[(size_t)MTOT * HID];
__device__ __nv_bfloat16 g_vl[(size_t)MTOT * HID];
__device__ __nv_bfloat16 g_wqh[(size_t)HID * HID];
__device__ __nv_bfloat16 g_wql[(size_t)HID * HID];
__device__ __nv_bfloat16 g_wkh[(size_t)HID * HID];
__device__ __nv_bfloat16 g_wkl[(size_t)HID * HID];
__device__ __nv_bfloat16 g_wvh[(size_t)HID * HID];
__device__ __nv_bfloat16 g_wvl[(size_t)HID * HID];
__device__ __nv_bfloat16 g_woh[(size_t)HID * HID];
__device__ __nv_bfloat16 g_wol[(size_t)HID * HID];

// ---------------- low-level helpers -----------------------------------------
__device__ __forceinline__ uint32_t smem_u32(const void* p) {
    uint32_t a;
    asm("{ .reg .u64 t; cvta.to.shared.u64 t, %1; cvt.u32.u64 %0, t; }"
        : "=r"(a) : "l"(p));
    return a;
}

__device__ __forceinline__ void mma16816(float* c, const uint32_t* a, const uint32_t* b) {
    asm volatile(
        "mma.sync.aligned.m16n8k16.row.col.f32.bf16.bf16.f32 "
        "{%0,%1,%2,%3}, {%4,%5,%6,%7}, {%8,%9}, {%0,%1,%2,%3};"
        : "+f"(c[0]), "+f"(c[1]), "+f"(c[2]), "+f"(c[3])
        : "r"(a[0]), "r"(a[1]), "r"(a[2]), "r"(a[3]), "r"(b[0]), "r"(b[1]));
}

__device__ __forceinline__ void split2(float x0, float x1, uint32_t& h, uint32_t& l) {
    __nv_bfloat16 h0 = __float2bfloat16_rn(x0);
    __nv_bfloat16 h1 = __float2bfloat16_rn(x1);
    __nv_bfloat162 hv; hv.x = h0; hv.y = h1;
    __nv_bfloat162 lv = __floats2bfloat162_rn(x0 - __bfloat162float(h0),
                                              x1 - __bfloat162float(h1));
    h = *(uint32_t*)&hv;
    l = *(uint32_t*)&lv;
}

__device__ __forceinline__ uint32_t lds32a(uint32_t a) {
    uint32_t v; asm volatile("ld.shared.b32 %0, [%1];" : "=r"(v) : "r"(a)); return v;
}

__device__ __forceinline__ void ldsm2t(uint32_t& r0, uint32_t& r1, uint32_t saddr) {
    asm volatile("ldmatrix.sync.aligned.m8n8.x2.trans.shared.b16 {%0,%1}, [%2];"
                 : "=r"(r0), "=r"(r1) : "r"(saddr));
}

__device__ __forceinline__ void cpa16(uint32_t dst, const void* src) {
    asm volatile("cp.async.cg.shared.global [%0], [%1], 16;" :: "r"(dst), "l"(src));
}
#define CP_COMMIT asm volatile("cp.async.commit_group;" ::: "memory")
#define CP_WAIT0 asm volatile("cp.async.wait_group 0;" ::: "memory")
#define CP_WAIT1 asm volatile("cp.async.wait_group 1;" ::: "memory")

// ---------------- split: fp32 -> bf16 hi/lo ----------------------------------
__global__ void split_kernel(const float* __restrict__ s, __nv_bfloat16* __restrict__ h,
                             __nv_bfloat16* __restrict__ l, int n4)
{
    int i = blockIdx.x * blockDim.x + threadIdx.x;
    if (i >= n4) return;
    float4 v = ((const float4*)s)[i];
    uint32_t h0, l0, h1, l1;
    split2(v.x, v.y, h0, l0);
    split2(v.z, v.w, h1, l1);
    ((uint32_t*)h)[i * 2]     = h0;
    ((uint32_t*)h)[i * 2 + 1] = h1;
    ((uint32_t*)l)[i * 2]     = l0;
    ((uint32_t*)l)[i * 2 + 1] = l1;
}

// ============== pipelined MMA GEMM: C = A @ W, bf16x3 pre-split =============
// CTA 128x128, K-chunk 32, 2-stage cp.async. A smem [128][40], B smem [32][136].
#define GOFF_AH 0
#define GOFF_AL 10240
#define GOFF_BH 20480
#define GOFF_BL 29184
#define GSTAGE  37888
#define GEMM_SMEM (2*GSTAGE)

__device__ __forceinline__ void gemm_fill(uint32_t sb, int s,
    const __nv_bfloat16* __restrict__ aH, const __nv_bfloat16* __restrict__ aL,
    const __nv_bfloat16* __restrict__ bH, const __nv_bfloat16* __restrict__ bL,
    int m0, int n0, int k0, int tid)
{
    uint32_t st = sb + s * GSTAGE;
#pragma unroll
    for (int rep = 0; rep < 2; rep++) {
        int i = tid + rep * 256;
        {   // A: 128 rows x 4 16B-chunks (hi+lo)
            int r = i >> 2, c = i & 3;
            uint32_t off = (uint32_t)(r * 80 + c * 16);
            size_t g = (size_t)(m0 + r) * HID + k0 + c * 8;
            cpa16(st + GOFF_AH + off, aH + g);
            cpa16(st + GOFF_AL + off, aL + g);
        }
        {   // B: 32 rows x 16 chunks (hi+lo), row-major [k][n]
            int r = i >> 4, c = i & 15;
            uint32_t off = (uint32_t)(r * 272 + c * 16);
            size_t g = (size_t)(k0 + r) * HID + n0 + c * 8;
            cpa16(st + GOFF_BH + off, bH + g);
            cpa16(st + GOFF_BL + off, bL + g);
        }
    }
}

__device__ __forceinline__ void mma_gemm_body(
    const __nv_bfloat16* __restrict__ aH, const __nv_bfloat16* __restrict__ aL,
    const __nv_bfloat16* __restrict__ bH, const __nv_bfloat16* __restrict__ bL,
    float* __restrict__ C, int m0, int n0)
{
    extern __shared__ char smem[];
    const uint32_t sb = smem_u32(smem);
    const int tid = threadIdx.x;
    const int lane = tid & 31;
    const int wid = tid >> 5;
    const int wm = wid & 3;
    const int wn = wid >> 2;

    float c[2][8][4];
#pragma unroll
    for (int mt = 0; mt < 2; mt++)
#pragma unroll
        for (int nt = 0; nt < 8; nt++)
#pragma unroll
            for (int e = 0; e < 4; e++) c[mt][nt][e] = 0.f;

    gemm_fill(sb, 0, aH, aL, bH, bL, m0, n0, 0, tid);
    CP_COMMIT;

    const int NCH = HID / 32;   // 36
    for (int ch = 0; ch < NCH; ch++) {
        const int s = ch & 1;
        if (ch + 1 < NCH) {
            gemm_fill(sb, s ^ 1, aH, aL, bH, bL, m0, n0, (ch + 1) * 32, tid);
            CP_COMMIT;
            CP_WAIT1;
        } else {
            CP_WAIT0;
        }
        __syncthreads();

        const uint32_t aBh = sb + s * GSTAGE + GOFF_AH;
        const uint32_t aBl = sb + s * GSTAGE + GOFF_AL;
        const uint32_t bBh = sb + s * GSTAGE + GOFF_BH;
        const uint32_t bBl = sb + s * GSTAGE + GOFF_BL;

#pragma unroll
        for (int ks = 0; ks < 2; ks++) {
            const int kk = ks * 16 + (lane & 3) * 2;
            uint32_t fah[2][4], fal[2][4];
#pragma unroll
            for (int mt = 0; mt < 2; mt++) {
                int r0 = wm * 32 + mt * 16 + (lane >> 2);
                uint32_t o0 = (uint32_t)(r0 * 40 + kk) * 2;
                uint32_t o1 = o0 + 8 * 80;
                fah[mt][0] = lds32a(aBh + o0);      fah[mt][1] = lds32a(aBh + o1);
                fah[mt][2] = lds32a(aBh + o0 + 16); fah[mt][3] = lds32a(aBh + o1 + 16);
                fal[mt][0] = lds32a(aBl + o0);      fal[mt][1] = lds32a(aBl + o1);
                fal[mt][2] = lds32a(aBl + o0 + 16); fal[mt][3] = lds32a(aBl + o1 + 16);
            }
#pragma unroll
            for (int nt = 0; nt < 8; nt++) {
                uint32_t bo = (uint32_t)((ks * 16 + (lane & 15)) * 136
                                         + wn * 64 + nt * 8) * 2;
                uint32_t fbh[2], fbl[2];
                ldsm2t(fbh[0], fbh[1], bBh + bo);
                ldsm2t(fbl[0], fbl[1], bBl + bo);
#pragma unroll
                for (int mt = 0; mt < 2; mt++) {
                    mma16816(c[mt][nt], fah[mt], fbh);
                    mma16816(c[mt][nt], fah[mt], fbl);
                    mma16816(c[mt][nt], fal[mt], fbh);
                }
            }
        }
        __syncthreads();
    }

#pragma unroll
    for (int mt = 0; mt < 2; mt++) {
#pragma unroll
        for (int nt = 0; nt < 8; nt++) {
            int row = m0 + wm * 32 + mt * 16 + (lane >> 2);
            int col = n0 + wn * 64 + nt * 8 + (lane & 3) * 2;
            *(float2*)(C + (size_t)row * HID + col) =
                make_float2(c[mt][nt][0], c[mt][nt][1]);
            *(float2*)(C + (size_t)(row + 8) * HID + col) =
                make_float2(c[mt][nt][2], c[mt][nt][3]);
        }
    }
}

__global__ __launch_bounds__(256, 2)
void mma_gemm_qkv(const __nv_bfloat16* __restrict__ aH, const __nv_bfloat16* __restrict__ aL,
                  const __nv_bfloat16* __restrict__ qWh, const __nv_bfloat16* __restrict__ qWl,
                  const __nv_bfloat16* __restrict__ kWh, const __nv_bfloat16* __restrict__ kWl,
                  const __nv_bfloat16* __restrict__ vWh, const __nv_bfloat16* __restrict__ vWl,
                  float* __restrict__ q, float* __restrict__ k, float* __restrict__ v)
{
    const __nv_bfloat16* wH = (blockIdx.z == 0) ? qWh : (blockIdx.z == 1) ? kWh : vWh;
    const __nv_bfloat16* wL = (blockIdx.z == 0) ? qWl : (blockIdx.z == 1) ? kWl : vWl;
    float* C = (blockIdx.z == 0) ? q : (blockIdx.z == 1) ? k : v;
    mma_gemm_body(aH, aL, wH, wL, C, blockIdx.y * 128, blockIdx.x * 128);
}

__global__ __launch_bounds__(256, 2)
void mma_gemm_one(const __nv_bfloat16* __restrict__ aH, const __nv_bfloat16* __restrict__ aL,
                  const __nv_bfloat16* __restrict__ wH, const __nv_bfloat16* __restrict__ wL,
                  float* __restrict__ C)
{
    mma_gemm_body(aH, aL, wH, wL, C, blockIdx.y * 128, blockIdx.x * 128);
}

// ------------- fused RMSNorm (+weight) + 2D RoPE + bf16 hi/lo split ---------
__global__ void norm_rope_split(const float* __restrict__ q, const float* __restrict__ k,
                                const float* __restrict__ v,
                                const float* __restrict__ cosb,
                                const float* __restrict__ sinb,
                                const float* __restrict__ qw,
                                const float* __restrict__ kw,
                                __nv_bfloat16* __restrict__ qh, __nv_bfloat16* __restrict__ ql,
                                __nv_bfloat16* __restrict__ kh, __nv_bfloat16* __restrict__ kl,
                                __nv_bfloat16* __restrict__ vh, __nv_bfloat16* __restrict__ vl)
{
    __shared__ float sm[8][HD];
    int warp = threadIdx.x >> 5;
    int lane = threadIdx.x & 31;
    int gid = blockIdx.x * 8 + warp;
    int bp = gid >> 4;
    int h  = gid & 15;
    size_t base  = (size_t)bp * HID + (size_t)h * HD;
    size_t cbase = (size_t)bp * HD;

    float c0 = cosb[cbase + lane],      s0 = sinb[cbase + lane];
    float c1 = cosb[cbase + 32 + lane], s1 = sinb[cbase + 32 + lane];
    float c2 = 0.f, s2 = 0.f;
    if (lane < 8) { c2 = cosb[cbase + 64 + lane]; s2 = sinb[cbase + 64 + lane]; }

#pragma unroll
    for (int t = 0; t < 2; t++) {
        const float* buf = (t == 0) ? q : k;
        const float* w = (t == 0) ? qw : kw;
        __nv_bfloat16* oh = (t == 0) ? qh : kh;
        __nv_bfloat16* ol = (t == 0) ? ql : kl;
        float x0 = buf[base + lane];
        float x1 = buf[base + 32 + lane];
        float x2 = (lane < 8) ? buf[base + 64 + lane] : 0.f;
        float ss = x0 * x0 + x1 * x1 + x2 * x2;
#pragma unroll
        for (int m = 16; m; m >>= 1) ss += __shfl_xor_sync(0xffffffffu, ss, m);
        float r = rsqrtf(ss * (1.0f / 72.0f) + 1e-6f);
        sm[warp][lane]      = x0 * r * w[lane];
        sm[warp][lane + 32] = x1 * r * w[lane + 32];
        if (lane < 8) sm[warp][lane + 64] = x2 * r * w[lane + 64];
        __syncwarp();
        {
            int d = lane;
            int jj = (d < 36) ? d : d - 36;
            float rh = (jj < 18) ? -sm[warp][d + 18] : sm[warp][d - 18];
            float out = sm[warp][d] * c0 + rh * s0;
            __nv_bfloat16 hh = __float2bfloat16_rn(out);
            oh[base + d] = hh;
            ol[base + d] = __float2bfloat16_rn(out - __bfloat162float(hh));
        }
        {
            int d = lane + 32;
            int jj = (d < 36) ? d : d - 36;
            float rh = (jj < 18) ? -sm[warp][d + 18] : sm[warp][d - 18];
            float out = sm[warp][d] * c1 + rh * s1;
            __nv_bfloat16 hh = __float2bfloat16_rn(out);
            oh[base + d] = hh;
            ol[base + d] = __float2bfloat16_rn(out - __bfloat162float(hh));
        }
        if (lane < 8) {
            int d = lane + 64;
            int jj = d - 36;
            float rh = (jj < 18) ? -sm[warp][d + 18] : sm[warp][d - 18];
            float out = sm[warp][d] * c2 + rh * s2;
            __nv_bfloat16 hh = __float2bfloat16_rn(out);
            oh[base + d] = hh;
            ol[base + d] = __float2bfloat16_rn(out - __bfloat162float(hh));
        }
        __syncwarp();
    }
    {
        float x0 = v[base + lane];
        float x1 = v[base + 32 + lane];
        float x2 = (lane < 8) ? v[base + 64 + lane] : 0.f;
        float ss = x0 * x0 + x1 * x1 + x2 * x2;
#pragma unroll
        for (int m = 16; m; m >>= 1) ss += __shfl_xor_sync(0xffffffffu, ss, m);
        float r = rsqrtf(ss * (1.0f / 72.0f) + 1e-6f);
#pragma unroll
        for (int part = 0; part < 3; part++) {
            int d = lane + part * 32;
            if (d < HD) {
                float out = ((part == 0) ? x0 : (part == 1) ? x1 : x2) * r;
                __nv_bfloat16 hh = __float2bfloat16_rn(out);
                vh[base + d] = hh;
                vl[base + d] = __float2bfloat16_rn(out - __bfloat162float(hh));
            }
        }
    }
}

// ---------------- pipelined flash attention (mma.sync bf16x3) ---------------
// CTA: 128 queries x one head, 8 warps. Key tiles of 64, 2-stage cp.async.
// K smem [64][88] hi/lo (pad cols 72..79 zeroed once), V smem [64][72] row-major,
// V fragments via ldmatrix.x2.trans.
#define AOFF_KH 0
#define AOFF_KL 11264
#define AOFF_VH 22528
#define AOFF_VL 31744
#define ASTAGE  40960
#define ATTN_SMEM (2*ASTAGE)

__device__ __forceinline__ void attn_fill(uint32_t sb, int s,
    const __nv_bfloat16* __restrict__ kh, const __nv_bfloat16* __restrict__ kl,
    const __nv_bfloat16* __restrict__ vh, const __nv_bfloat16* __restrict__ vl,
    size_t kb, size_t hoff, int tid)
{
    uint32_t st = sb + s * ASTAGE;
    for (int i = tid; i < 576; i += 256) {
        int r = i / 9, c = i - r * 9;
        size_t g = (kb + r) * HID + hoff + c * 8;
        uint32_t ko = (uint32_t)(r * 176 + c * 16);
        uint32_t vo = (uint32_t)(r * 144 + c * 16);
        cpa16(st + AOFF_KH + ko, kh + g);
        cpa16(st + AOFF_KL + ko, kl + g);
        cpa16(st + AOFF_VH + vo, vh + g);
        cpa16(st + AOFF_VL + vo, vl + g);
    }
}

__global__ __launch_bounds__(256)
void attn_mma(const __nv_bfloat16* __restrict__ qh, const __nv_bfloat16* __restrict__ ql,
              const __nv_bfloat16* __restrict__ kh, const __nv_bfloat16* __restrict__ kl,
              const __nv_bfloat16* __restrict__ vh, const __nv_bfloat16* __restrict__ vl,
              float* __restrict__ o)
{
    extern __shared__ char smem[];
    const uint32_t sb = smem_u32(smem);
    const int tid = threadIdx.x;
    const int lane = tid & 31;
    const int wid = tid >> 5;
    const int b = blockIdx.z, h = blockIdx.y;
    const int q0 = blockIdx.x * 128;
    const size_t rowbase = (size_t)b * PP;
    const size_t hoff = (size_t)h * HD;

    // zero K pad cols 72..79 for both arrays x both stages (never overwritten)
    {
        int r = tid & 63;
        int which = tid >> 6;          // 0..3
        uint32_t base = sb + (which >> 1) * ASTAGE
                        + ((which & 1) ? AOFF_KL : AOFF_KH);
        uint32_t addr = base + (uint32_t)(r * 176 + 144);
        asm volatile("st.shared.v4.b32 [%0], {%1,%1,%1,%1};" :: "r"(addr), "r"(0u));
    }

    attn_fill(sb, 0, kh, kl, vh, vl, rowbase, hoff, tid);
    CP_COMMIT;

    // ---- Q fragments, register resident (hi & lo) ----
    uint32_t qfh[5][4], qfl[5][4];
    {
        int ra = q0 + wid * 16 + (lane >> 2);
        const size_t ga = (rowbase + ra) * HID + hoff;
        const size_t gb = ga + (size_t)8 * HID;
#pragma unroll
        for (int ks = 0; ks < 5; ks++) {
            int kk = ks * 16 + (lane & 3) * 2;
            qfh[ks][0] = *(const uint32_t*)(qh + ga + kk);
            qfh[ks][1] = *(const uint32_t*)(qh + gb + kk);
            qfl[ks][0] = *(const uint32_t*)(ql + ga + kk);
            qfl[ks][1] = *(const uint32_t*)(ql + gb + kk);
            if (ks < 4) {
                qfh[ks][2] = *(const uint32_t*)(qh + ga + kk + 8);
                qfh[ks][3] = *(const uint32_t*)(qh + gb + kk + 8);
                qfl[ks][2] = *(const uint32_t*)(ql + ga + kk + 8);
                qfl[ks][3] = *(const uint32_t*)(ql + gb + kk + 8);
            } else {
                qfh[ks][2] = qfh[ks][3] = 0u;
                qfl[ks][2] = qfl[ks][3] = 0u;
            }
        }
    }

    float m0 = -1e30f, m1 = -1e30f, l0 = 0.f, l1 = 0.f;
    float oacc[9][4];
#pragma unroll
    for (int dt = 0; dt < 9; dt++)
#pragma unroll
        for (int e = 0; e < 4; e++) oacc[dt][e] = 0.f;

    const int NT = PP / 64;   // 64
    for (int kt = 0; kt < NT; kt++) {
        const int s = kt & 1;
        if (kt + 1 < NT) {
            attn_fill(sb, s ^ 1, kh, kl, vh, vl, rowbase + (kt + 1) * 64, hoff, tid);
            CP_COMMIT;
            CP_WAIT1;
        } else {
            CP_WAIT0;
        }
        __syncthreads();

        const uint32_t kBh = sb + s * ASTAGE + AOFF_KH;
        const uint32_t kBl = sb + s * ASTAGE + AOFF_KL;
        const uint32_t vBh = sb + s * ASTAGE + AOFF_VH;
        const uint32_t vBl = sb + s * ASTAGE + AOFF_VL;

        // ---- S = Q K^T ----
        float sv[8][4];
#pragma unroll
        for (int nt = 0; nt < 8; nt++)
#pragma unroll
            for (int e = 0; e < 4; e++) sv[nt][e] = 0.f;

#pragma unroll
        for (int ks = 0; ks < 5; ks++) {
            const int kk = ks * 16 + (lane & 3) * 2;
#pragma unroll
            for (int nt = 0; nt < 8; nt++) {
                int key = nt * 8 + (lane >> 2);
                uint32_t ko = (uint32_t)(key * 88 + kk) * 2;
                uint32_t fbh[2] = { lds32a(kBh + ko), lds32a(kBh + ko + 16) };
                uint32_t fbl[2] = { lds32a(kBl + ko), lds32a(kBl + ko + 16) };
                mma16816(sv[nt], qfh[ks], fbh);
                mma16816(sv[nt], qfh[ks], fbl);
                mma16816(sv[nt], qfl[ks], fbh);
            }
        }

        // ---- online softmax ----
        float mx0 = -1e30f, mx1 = -1e30f;
#pragma unroll
        for (int nt = 0; nt < 8; nt++) {
            mx0 = fmaxf(mx0, fmaxf(sv[nt][0], sv[nt][1]));
            mx1 = fmaxf(mx1, fmaxf(sv[nt][2], sv[nt][3]));
        }
        mx0 = fmaxf(mx0, __shfl_xor_sync(0xffffffffu, mx0, 1));
        mx0 = fmaxf(mx0, __shfl_xor_sync(0xffffffffu, mx0, 2));
        mx1 = fmaxf(mx1, __shfl_xor_sync(0xffffffffu, mx1, 1));
        mx1 = fmaxf(mx1, __shfl_xor_sync(0xffffffffu, mx1, 2));
        float nm0 = fmaxf(m0, mx0), nm1 = fmaxf(m1, mx1);
        float a0 = __expf(m0 - nm0), a1 = __expf(m1 - nm1);
        m0 = nm0; m1 = nm1;
        float rs0 = 0.f, rs1 = 0.f;
#pragma unroll
        for (int nt = 0; nt < 8; nt++) {
            sv[nt][0] = __expf(sv[nt][0] - nm0);
            sv[nt][1] = __expf(sv[nt][1] - nm0);
            sv[nt][2] = __expf(sv[nt][2] - nm1);
            sv[nt][3] = __expf(sv[nt][3] - nm1);
            rs0 += sv[nt][0] + sv[nt][1];
            rs1 += sv[nt][2] + sv[nt][3];
        }
        rs0 += __shfl_xor_sync(0xffffffffu, rs0, 1);
        rs0 += __shfl_xor_sync(0xffffffffu, rs0, 2);
        rs1 += __shfl_xor_sync(0xffffffffu, rs1, 1);
        rs1 += __shfl_xor_sync(0xffffffffu, rs1, 2);
        l0 = l0 * a0 + rs0;
        l1 = l1 * a1 + rs1;
#pragma unroll
        for (int dt = 0; dt < 9; dt++) {
            oacc[dt][0] *= a0; oacc[dt][1] *= a0;
            oacc[dt][2] *= a1; oacc[dt][3] *= a1;
        }

        // ---- O += P V (V B-fragments via ldmatrix.trans) ----
#pragma unroll
        for (int pk = 0; pk < 4; pk++) {
            uint32_t aph[4], apl[4];
            split2(sv[2 * pk][0],     sv[2 * pk][1],     aph[0], apl[0]);
            split2(sv[2 * pk][2],     sv[2 * pk][3],     aph[1], apl[1]);
            split2(sv[2 * pk + 1][0], sv[2 * pk + 1][1], aph[2], apl[2]);
            split2(sv[2 * pk + 1][2], sv[2 * pk + 1][3], aph[3], apl[3]);
            uint32_t rowoff = (uint32_t)((pk * 16 + (lane & 15)) * 72) * 2;
#pragma unroll
            for (int dt = 0; dt < 9; dt++) {
                uint32_t vo = rowoff + (uint32_t)(dt * 8) * 2;
                uint32_t fvh[2], fvl[2];
                ldsm2t(fvh[0], fvh[1], vBh + vo);
                ldsm2t(fvl[0], fvl[1], vBl + vo);
                mma16816(oacc[dt], aph, fvh);
                mma16816(oacc[dt], aph, fvl);
                mma16816(oacc[dt], apl, fvh);
            }
        }
        __syncthreads();
    }

    // ---- epilogue ----
    float il0 = 1.0f / l0, il1 = 1.0f / l1;
    int ra = q0 + wid * 16 + (lane >> 2);
#pragma unroll
    for (int dt = 0; dt < 9; dt++) {
        int col = dt * 8 + (lane & 3) * 2;
        *(float2*)(o + (rowbase + ra) * HID + hoff + col) =
            make_float2(oacc[dt][0] * il0, oacc[dt][1] * il0);
        *(float2*)(o + (rowbase + ra + 8) * HID + hoff + col) =
            make_float2(oacc[dt][2] * il1, oacc[dt][3] * il1);
    }
}

// ---------------------------------- launch ----------------------------------
extern "C" void kernel_launch(void* const* d_in, const int* in_sizes, int n_in,
                              void* d_out, int out_size)
{
    const float* hidden = (const float*)d_in[0];
    const float* cosb   = (const float*)d_in[1];
    const float* sinb   = (const float*)d_in[2];
    const float* Wq     = (const float*)d_in[3];
    const float* Wk     = (const float*)d_in[4];
    const float* Wv     = (const float*)d_in[5];
    const float* Wo     = (const float*)d_in[6];
    const float* qw     = (const float*)d_in[7];
    const float* kw     = (const float*)d_in[8];
    float* out = (float*)d_out;

    float *q, *k, *v, *o;
    __nv_bfloat16 *hh, *hl, *qh, *ql, *kh, *kl, *vh, *vl;
    __nv_bfloat16 *wqh, *wql, *wkh, *wkl, *wvh, *wvl, *woh, *wol;
    cudaGetSymbolAddress((void**)&q, g_q);
    cudaGetSymbolAddress((void**)&k, g_k);
    cudaGetSymbolAddress((void**)&v, g_v);
    cudaGetSymbolAddress((void**)&o, g_o);
    cudaGetSymbolAddress((void**)&hh, g_hh);
    cudaGetSymbolAddress((void**)&hl, g_hl);
    cudaGetSymbolAddress((void**)&qh, g_qh);
    cudaGetSymbolAddress((void**)&ql, g_ql);
    cudaGetSymbolAddress((void**)&kh, g_kh);
    cudaGetSymbolAddress((void**)&kl, g_kl);
    cudaGetSymbolAddress((void**)&vh, g_vh);
    cudaGetSymbolAddress((void**)&vl, g_vl);
    cudaGetSymbolAddress((void**)&wqh, g_wqh);
    cudaGetSymbolAddress((void**)&wql, g_wql);
    cudaGetSymbolAddress((void**)&wkh, g_wkh);
    cudaGetSymbolAddress((void**)&wkl, g_wkl);
    cudaGetSymbolAddress((void**)&wvh, g_wvh);
    cudaGetSymbolAddress((void**)&wvl, g_wvl);
    cudaGetSymbolAddress((void**)&woh, g_woh);
    cudaGetSymbolAddress((void**)&wol, g_wol);

    cudaFuncSetAttribute(mma_gemm_qkv, cudaFuncAttributeMaxDynamicSharedMemorySize,
                         GEMM_SMEM);
    cudaFuncSetAttribute(mma_gemm_one, cudaFuncAttributeMaxDynamicSharedMemorySize,
                         GEMM_SMEM);
    cudaFuncSetAttribute(attn_mma, cudaFuncAttributeMaxDynamicSharedMemorySize,
                         ATTN_SMEM);

    const int NH4 = (MTOT * HID) / 4;      // 2359296
    const int NW4 = (HID * HID) / 4;       // 331776

    // pre-split inputs
    split_kernel<<<NH4 / 256, 256>>>(hidden, hh, hl, NH4);
    split_kernel<<<NW4 / 256, 256>>>(Wq, wqh, wql, NW4);
    split_kernel<<<NW4 / 256, 256>>>(Wk, wkh, wkl, NW4);
    split_kernel<<<NW4 / 256, 256>>>(Wv, wvh, wvl, NW4);
    split_kernel<<<NW4 / 256, 256>>>(Wo, woh, wol, NW4);

    dim3 qkvgrid(HID / 128, MTOT / 128, 3);
    mma_gemm_qkv<<<qkvgrid, 256, GEMM_SMEM>>>(hh, hl, wqh, wql, wkh, wkl,
                                              wvh, wvl, q, k, v);

    norm_rope_split<<<(BB * PP * NH) / 8, 256>>>(q, k, v, cosb, sinb, qw, kw,
                                                 qh, ql, kh, kl, vh, vl);

    dim3 agrid(PP / 128, NH, BB);
    attn_mma<<<agrid, 256, ATTN_SMEM>>>(qh, ql, kh, kl, vh, vl, o);

    // split o (reuse hidden hi/lo buffers) and final projection
    split_kernel<<<NH4 / 256, 256>>>(o, hh, hl, NH4);
    dim3 ogrid(HID / 128, MTOT / 128);
    mma_gemm_one<<<ogrid, 256, GEMM_SMEM>>>(hh, hl, woh, wol, out);
}

// round 5
// speedup vs baseline: 3.7412x; 1.0899x over previous
#include <cuda_runtime.h>
#include <cuda_bf16.h>
#include <math.h>
#include <stdint.h>

#define BB 2
#define PP 4096
#define HID 1152
#define NH 16
#define HD 72
#define MTOT (BB*PP)            // 8192

// ---------------- scratch (device globals; no allocations allowed) ----------
__device__ float g_q[(size_t)MTOT * HID];
__device__ float g_k[(size_t)MTOT * HID];
__device__ float g_v[(size_t)MTOT * HID];
__device__ __nv_bfloat16 g_hh[(size_t)MTOT * HID];   // hidden hi (reused for o hi)
__device__ __nv_bfloat16 g_hl[(size_t)MTOT * HID];   // hidden lo (reused for o lo)
__device__ __nv_bfloat16 g_qh[(size_t)MTOT * HID];
__device__ __nv_bfloat16 g_ql[(size_t)MTOT * HID];
__device__ __nv_bfloat16 g_kh[(size_t)MTOT * HID];
__device__ __nv_bfloat16 g_kl[(size_t)MTOT * HID];
__device__ __nv_bfloat16 g_vh[(size_t)MTOT * HID];
__device__ __nv_bfloat16 g_vl[(size_t)MTOT * HID];
__device__ __nv_bfloat16 g_wqh[(size_t)HID * HID];
__device__ __nv_bfloat16 g_wql[(size_t)HID * HID];
__device__ __nv_bfloat16 g_wkh[(size_t)HID * HID];
__device__ __nv_bfloat16 g_wkl[(size_t)HID * HID];
__device__ __nv_bfloat16 g_wvh[(size_t)HID * HID];
__device__ __nv_bfloat16 g_wvl[(size_t)HID * HID];
__device__ __nv_bfloat16 g_woh[(size_t)HID * HID];
__device__ __nv_bfloat16 g_wol[(size_t)HID * HID];

// ---------------- low-level helpers -----------------------------------------
__device__ __forceinline__ uint32_t smem_u32(const void* p) {
    uint32_t a;
    asm("{ .reg .u64 t; cvta.to.shared.u64 t, %1; cvt.u32.u64 %0, t; }"
        : "=r"(a) : "l"(p));
    return a;
}

__device__ __forceinline__ void mma16816(float* c, const uint32_t* a, const uint32_t* b) {
    asm volatile(
        "mma.sync.aligned.m16n8k16.row.col.f32.bf16.bf16.f32 "
        "{%0,%1,%2,%3}, {%4,%5,%6,%7}, {%8,%9}, {%0,%1,%2,%3};"
        : "+f"(c[0]), "+f"(c[1]), "+f"(c[2]), "+f"(c[3])
        : "r"(a[0]), "r"(a[1]), "r"(a[2]), "r"(a[3]), "r"(b[0]), "r"(b[1]));
}

__device__ __forceinline__ void mma16808(float* c, const uint32_t* a, uint32_t b) {
    asm volatile(
        "mma.sync.aligned.m16n8k8.row.col.f32.bf16.bf16.f32 "
        "{%0,%1,%2,%3}, {%4,%5}, {%6}, {%0,%1,%2,%3};"
        : "+f"(c[0]), "+f"(c[1]), "+f"(c[2]), "+f"(c[3])
        : "r"(a[0]), "r"(a[1]), "r"(b));
}

__device__ __forceinline__ void split2(float x0, float x1, uint32_t& h, uint32_t& l) {
    __nv_bfloat16 h0 = __float2bfloat16_rn(x0);
    __nv_bfloat16 h1 = __float2bfloat16_rn(x1);
    __nv_bfloat162 hv; hv.x = h0; hv.y = h1;
    __nv_bfloat162 lv = __floats2bfloat162_rn(x0 - __bfloat162float(h0),
                                              x1 - __bfloat162float(h1));
    h = *(uint32_t*)&hv;
    l = *(uint32_t*)&lv;
}

__device__ __forceinline__ uint32_t lds32a(uint32_t a) {
    uint32_t v; asm volatile("ld.shared.b32 %0, [%1];" : "=r"(v) : "r"(a)); return v;
}

__device__ __forceinline__ void ldsm1(uint32_t& r, uint32_t a) {
    asm volatile("ldmatrix.sync.aligned.m8n8.x1.shared.b16 {%0}, [%1];"
                 : "=r"(r) : "r"(a));
}
__device__ __forceinline__ void ldsm2(uint32_t* r, uint32_t a) {
    asm volatile("ldmatrix.sync.aligned.m8n8.x2.shared.b16 {%0,%1}, [%2];"
                 : "=r"(r[0]), "=r"(r[1]) : "r"(a));
}
__device__ __forceinline__ void ldsm2t(uint32_t* r, uint32_t a) {
    asm volatile("ldmatrix.sync.aligned.m8n8.x2.trans.shared.b16 {%0,%1}, [%2];"
                 : "=r"(r[0]), "=r"(r[1]) : "r"(a));
}
__device__ __forceinline__ void ldsm4t(uint32_t* r, uint32_t a) {
    asm volatile("ldmatrix.sync.aligned.m8n8.x4.trans.shared.b16 {%0,%1,%2,%3}, [%4];"
                 : "=r"(r[0]), "=r"(r[1]), "=r"(r[2]), "=r"(r[3]) : "r"(a));
}

__device__ __forceinline__ void cpa16(uint32_t dst, const void* src) {
    asm volatile("cp.async.cg.shared.global [%0], [%1], 16;" :: "r"(dst), "l"(src));
}
#define CP_COMMIT asm volatile("cp.async.commit_group;" ::: "memory")
#define CP_WAIT0 asm volatile("cp.async.wait_group 0;" ::: "memory")
#define CP_WAIT1 asm volatile("cp.async.wait_group 1;" ::: "memory")

// ---------------- split: fp32 -> bf16 hi/lo ----------------------------------
__global__ void split_kernel(const float* __restrict__ s, __nv_bfloat16* __restrict__ h,
                             __nv_bfloat16* __restrict__ l, int n4)
{
    int i = blockIdx.x * blockDim.x + threadIdx.x;
    if (i >= n4) return;
    float4 v = ((const float4*)s)[i];
    uint32_t h0, l0, h1, l1;
    split2(v.x, v.y, h0, l0);
    split2(v.z, v.w, h1, l1);
    ((uint32_t*)h)[i * 2]     = h0;
    ((uint32_t*)h)[i * 2 + 1] = h1;
    ((uint32_t*)l)[i * 2]     = l0;
    ((uint32_t*)l)[i * 2 + 1] = l1;
}

// ============== pipelined MMA GEMM: C = A @ W, bf16x3 pre-split =============
#define GOFF_AH 0
#define GOFF_AL 10240
#define GOFF_BH 20480
#define GOFF_BL 29184
#define GSTAGE  37888
#define GEMM_SMEM (2*GSTAGE)

__device__ __forceinline__ void gemm_fill(uint32_t sb, int s,
    const __nv_bfloat16* __restrict__ aH, const __nv_bfloat16* __restrict__ aL,
    const __nv_bfloat16* __restrict__ bH, const __nv_bfloat16* __restrict__ bL,
    int m0, int n0, int k0, int tid)
{
    uint32_t st = sb + s * GSTAGE;
#pragma unroll
    for (int rep = 0; rep < 2; rep++) {
        int i = tid + rep * 256;
        {
            int r = i >> 2, c = i & 3;
            uint32_t off = (uint32_t)(r * 80 + c * 16);
            size_t g = (size_t)(m0 + r) * HID + k0 + c * 8;
            cpa16(st + GOFF_AH + off, aH + g);
            cpa16(st + GOFF_AL + off, aL + g);
        }
        {
            int r = i >> 4, c = i & 15;
            uint32_t off = (uint32_t)(r * 272 + c * 16);
            size_t g = (size_t)(k0 + r) * HID + n0 + c * 8;
            cpa16(st + GOFF_BH + off, bH + g);
            cpa16(st + GOFF_BL + off, bL + g);
        }
    }
}

__device__ __forceinline__ void mma_gemm_body(
    const __nv_bfloat16* __restrict__ aH, const __nv_bfloat16* __restrict__ aL,
    const __nv_bfloat16* __restrict__ bH, const __nv_bfloat16* __restrict__ bL,
    float* __restrict__ C, int m0, int n0)
{
    extern __shared__ char smem[];
    const uint32_t sb = smem_u32(smem);
    const int tid = threadIdx.x;
    const int lane = tid & 31;
    const int wid = tid >> 5;
    const int wm = wid & 3;
    const int wn = wid >> 2;

    float c[2][8][4];
#pragma unroll
    for (int mt = 0; mt < 2; mt++)
#pragma unroll
        for (int nt = 0; nt < 8; nt++)
#pragma unroll
            for (int e = 0; e < 4; e++) c[mt][nt][e] = 0.f;

    gemm_fill(sb, 0, aH, aL, bH, bL, m0, n0, 0, tid);
    CP_COMMIT;

    const int NCH = HID / 32;   // 36
    for (int ch = 0; ch < NCH; ch++) {
        const int s = ch & 1;
        if (ch + 1 < NCH) {
            gemm_fill(sb, s ^ 1, aH, aL, bH, bL, m0, n0, (ch + 1) * 32, tid);
            CP_COMMIT;
            CP_WAIT1;
        } else {
            CP_WAIT0;
        }
        __syncthreads();

        const uint32_t aBh = sb + s * GSTAGE + GOFF_AH;
        const uint32_t aBl = sb + s * GSTAGE + GOFF_AL;
        const uint32_t bBh = sb + s * GSTAGE + GOFF_BH;
        const uint32_t bBl = sb + s * GSTAGE + GOFF_BL;

#pragma unroll
        for (int ks = 0; ks < 2; ks++) {
            const int kk = ks * 16 + (lane & 3) * 2;
            uint32_t fah[2][4], fal[2][4];
#pragma unroll
            for (int mt = 0; mt < 2; mt++) {
                int r0 = wm * 32 + mt * 16 + (lane >> 2);
                uint32_t o0 = (uint32_t)(r0 * 40 + kk) * 2;
                uint32_t o1 = o0 + 8 * 80;
                fah[mt][0] = lds32a(aBh + o0);      fah[mt][1] = lds32a(aBh + o1);
                fah[mt][2] = lds32a(aBh + o0 + 16); fah[mt][3] = lds32a(aBh + o1 + 16);
                fal[mt][0] = lds32a(aBl + o0);      fal[mt][1] = lds32a(aBl + o1);
                fal[mt][2] = lds32a(aBl + o0 + 16); fal[mt][3] = lds32a(aBl + o1 + 16);
            }
#pragma unroll
            for (int nt = 0; nt < 8; nt++) {
                uint32_t bo = (uint32_t)((ks * 16 + (lane & 15)) * 136
                                         + wn * 64 + nt * 8) * 2;
                uint32_t fbh[2], fbl[2];
                ldsm2t(fbh, bBh + bo);
                ldsm2t(fbl, bBl + bo);
#pragma unroll
                for (int mt = 0; mt < 2; mt++) {
                    mma16816(c[mt][nt], fah[mt], fbh);
                    mma16816(c[mt][nt], fah[mt], fbl);
                    mma16816(c[mt][nt], fal[mt], fbh);
                }
            }
        }
        __syncthreads();
    }

#pragma unroll
    for (int mt = 0; mt < 2; mt++) {
#pragma unroll
        for (int nt = 0; nt < 8; nt++) {
            int row = m0 + wm * 32 + mt * 16 + (lane >> 2);
            int col = n0 + wn * 64 + nt * 8 + (lane & 3) * 2;
            *(float2*)(C + (size_t)row * HID + col) =
                make_float2(c[mt][nt][0], c[mt][nt][1]);
            *(float2*)(C + (size_t)(row + 8) * HID + col) =
                make_float2(c[mt][nt][2], c[mt][nt][3]);
        }
    }
}

__global__ __launch_bounds__(256, 2)
void mma_gemm_qkv(const __nv_bfloat16* __restrict__ aH, const __nv_bfloat16* __restrict__ aL,
                  const __nv_bfloat16* __restrict__ qWh, const __nv_bfloat16* __restrict__ qWl,
                  const __nv_bfloat16* __restrict__ kWh, const __nv_bfloat16* __restrict__ kWl,
                  const __nv_bfloat16* __restrict__ vWh, const __nv_bfloat16* __restrict__ vWl,
                  float* __restrict__ q, float* __restrict__ k, float* __restrict__ v)
{
    const __nv_bfloat16* wH = (blockIdx.z == 0) ? qWh : (blockIdx.z == 1) ? kWh : vWh;
    const __nv_bfloat16* wL = (blockIdx.z == 0) ? qWl : (blockIdx.z == 1) ? kWl : vWl;
    float* C = (blockIdx.z == 0) ? q : (blockIdx.z == 1) ? k : v;
    mma_gemm_body(aH, aL, wH, wL, C, blockIdx.y * 128, blockIdx.x * 128);
}

__global__ __launch_bounds__(256, 2)
void mma_gemm_out(const __nv_bfloat16* __restrict__ aH, const __nv_bfloat16* __restrict__ aL,
                  const __nv_bfloat16* __restrict__ wH, const __nv_bfloat16* __restrict__ wL,
                  float* __restrict__ C)
{
    mma_gemm_body(aH, aL, wH, wL, C, blockIdx.y * 128, blockIdx.x * 128);
}

// ------------- fused RMSNorm (+weight) + 2D RoPE + bf16 hi/lo split ---------
__global__ void norm_rope_split(const float* __restrict__ q, const float* __restrict__ k,
                                const float* __restrict__ v,
                                const float* __restrict__ cosb,
                                const float* __restrict__ sinb,
                                const float* __restrict__ qw,
                                const float* __restrict__ kw,
                                __nv_bfloat16* __restrict__ qh, __nv_bfloat16* __restrict__ ql,
                                __nv_bfloat16* __restrict__ kh, __nv_bfloat16* __restrict__ kl,
                                __nv_bfloat16* __restrict__ vh, __nv_bfloat16* __restrict__ vl)
{
    __shared__ float sm[8][HD];
    int warp = threadIdx.x >> 5;
    int lane = threadIdx.x & 31;
    int gid = blockIdx.x * 8 + warp;
    int bp = gid >> 4;
    int h  = gid & 15;
    size_t base  = (size_t)bp * HID + (size_t)h * HD;
    size_t cbase = (size_t)bp * HD;

    float c0 = cosb[cbase + lane],      s0 = sinb[cbase + lane];
    float c1 = cosb[cbase + 32 + lane], s1 = sinb[cbase + 32 + lane];
    float c2 = 0.f, s2 = 0.f;
    if (lane < 8) { c2 = cosb[cbase + 64 + lane]; s2 = sinb[cbase + 64 + lane]; }

#pragma unroll
    for (int t = 0; t < 2; t++) {
        const float* buf = (t == 0) ? q : k;
        const float* w = (t == 0) ? qw : kw;
        __nv_bfloat16* oh = (t == 0) ? qh : kh;
        __nv_bfloat16* ol = (t == 0) ? ql : kl;
        float x0 = buf[base + lane];
        float x1 = buf[base + 32 + lane];
        float x2 = (lane < 8) ? buf[base + 64 + lane] : 0.f;
        float ss = x0 * x0 + x1 * x1 + x2 * x2;
#pragma unroll
        for (int m = 16; m; m >>= 1) ss += __shfl_xor_sync(0xffffffffu, ss, m);
        float r = rsqrtf(ss * (1.0f / 72.0f) + 1e-6f);
        sm[warp][lane]      = x0 * r * w[lane];
        sm[warp][lane + 32] = x1 * r * w[lane + 32];
        if (lane < 8) sm[warp][lane + 64] = x2 * r * w[lane + 64];
        __syncwarp();
        {
            int d = lane;
            int jj = (d < 36) ? d : d - 36;
            float rh = (jj < 18) ? -sm[warp][d + 18] : sm[warp][d - 18];
            float out = sm[warp][d] * c0 + rh * s0;
            __nv_bfloat16 hh = __float2bfloat16_rn(out);
            oh[base + d] = hh;
            ol[base + d] = __float2bfloat16_rn(out - __bfloat162float(hh));
        }
        {
            int d = lane + 32;
            int jj = (d < 36) ? d : d - 36;
            float rh = (jj < 18) ? -sm[warp][d + 18] : sm[warp][d - 18];
            float out = sm[warp][d] * c1 + rh * s1;
            __nv_bfloat16 hh = __float2bfloat16_rn(out);
            oh[base + d] = hh;
            ol[base + d] = __float2bfloat16_rn(out - __bfloat162float(hh));
        }
        if (lane < 8) {
            int d = lane + 64;
            int jj = d - 36;
            float rh = (jj < 18) ? -sm[warp][d + 18] : sm[warp][d - 18];
            float out = sm[warp][d] * c2 + rh * s2;
            __nv_bfloat16 hh = __float2bfloat16_rn(out);
            oh[base + d] = hh;
            ol[base + d] = __float2bfloat16_rn(out - __bfloat162float(hh));
        }
        __syncwarp();
    }
    {
        float x0 = v[base + lane];
        float x1 = v[base + 32 + lane];
        float x2 = (lane < 8) ? v[base + 64 + lane] : 0.f;
        float ss = x0 * x0 + x1 * x1 + x2 * x2;
#pragma unroll
        for (int m = 16; m; m >>= 1) ss += __shfl_xor_sync(0xffffffffu, ss, m);
        float r = rsqrtf(ss * (1.0f / 72.0f) + 1e-6f);
#pragma unroll
        for (int part = 0; part < 3; part++) {
            int d = lane + part * 32;
            if (d < HD) {
                float out = ((part == 0) ? x0 : (part == 1) ? x1 : x2) * r;
                __nv_bfloat16 hh = __float2bfloat16_rn(out);
                vh[base + d] = hh;
                vl[base + d] = __float2bfloat16_rn(out - __bfloat162float(hh));
            }
        }
    }
}

// ---------------- pipelined flash attention (mma.sync bf16x3) ---------------
// K smem [64][88] hi/lo, V smem [64][72] row-major hi/lo, 2-stage cp.async.
// QK: k16 x4 steps + k8 tail (HD=72). All B-frags via ldmatrix.
#define AOFF_KH 0
#define AOFF_KL 11264
#define AOFF_VH 22528
#define AOFF_VL 31744
#define ASTAGE  40960
#define ATTN_SMEM (2*ASTAGE)

__device__ __forceinline__ void attn_fill(uint32_t sb, int s,
    const __nv_bfloat16* __restrict__ kh, const __nv_bfloat16* __restrict__ kl,
    const __nv_bfloat16* __restrict__ vh, const __nv_bfloat16* __restrict__ vl,
    size_t kb, size_t hoff, int tid)
{
    uint32_t st = sb + s * ASTAGE;
    for (int i = tid; i < 576; i += 256) {
        int r = i / 9, c = i - r * 9;
        size_t g = (kb + r) * HID + hoff + c * 8;
        uint32_t ko = (uint32_t)(r * 176 + c * 16);
        uint32_t vo = (uint32_t)(r * 144 + c * 16);
        cpa16(st + AOFF_KH + ko, kh + g);
        cpa16(st + AOFF_KL + ko, kl + g);
        cpa16(st + AOFF_VH + vo, vh + g);
        cpa16(st + AOFF_VL + vo, vl + g);
    }
}

__global__ __launch_bounds__(256, 2)
void attn_mma(const __nv_bfloat16* __restrict__ qh, const __nv_bfloat16* __restrict__ ql,
              const __nv_bfloat16* __restrict__ kh, const __nv_bfloat16* __restrict__ kl,
              const __nv_bfloat16* __restrict__ vh, const __nv_bfloat16* __restrict__ vl,
              __nv_bfloat16* __restrict__ oh, __nv_bfloat16* __restrict__ ol)
{
    extern __shared__ char smem[];
    const uint32_t sb = smem_u32(smem);
    const int tid = threadIdx.x;
    const int lane = tid & 31;
    const int wid = tid >> 5;
    const int b = blockIdx.z, h = blockIdx.y;
    const int q0 = blockIdx.x * 128;
    const size_t rowbase = (size_t)b * PP;
    const size_t hoff = (size_t)h * HD;

    attn_fill(sb, 0, kh, kl, vh, vl, rowbase, hoff, tid);
    CP_COMMIT;

    // ldmatrix lane-invariant address parts
    const uint32_t kinv  = (uint32_t)((lane & 7) * 176 + ((lane >> 3) & 1) * 16);
    const uint32_t k1inv = (uint32_t)((lane & 7) * 176);
    const uint32_t vinv  = (uint32_t)((lane & 15) * 144 + (lane >> 4) * 16);
    const uint32_t v2inv = (uint32_t)((lane & 15) * 144);

    // ---- Q fragments, register resident (hi & lo), k16 x4 + k8 tail ----
    uint32_t qfh[4][4], qfl[4][4], qth[2], qtl[2];
    {
        int ra = q0 + wid * 16 + (lane >> 2);
        const size_t ga = (rowbase + ra) * HID + hoff;
        const size_t gb = ga + (size_t)8 * HID;
        const int kof = (lane & 3) * 2;
#pragma unroll
        for (int ks = 0; ks < 4; ks++) {
            int kk = ks * 16 + kof;
            qfh[ks][0] = *(const uint32_t*)(qh + ga + kk);
            qfh[ks][1] = *(const uint32_t*)(qh + gb + kk);
            qfh[ks][2] = *(const uint32_t*)(qh + ga + kk + 8);
            qfh[ks][3] = *(const uint32_t*)(qh + gb + kk + 8);
            qfl[ks][0] = *(const uint32_t*)(ql + ga + kk);
            qfl[ks][1] = *(const uint32_t*)(ql + gb + kk);
            qfl[ks][2] = *(const uint32_t*)(ql + ga + kk + 8);
            qfl[ks][3] = *(const uint32_t*)(ql + gb + kk + 8);
        }
        qth[0] = *(const uint32_t*)(qh + ga + 64 + kof);
        qth[1] = *(const uint32_t*)(qh + gb + 64 + kof);
        qtl[0] = *(const uint32_t*)(ql + ga + 64 + kof);
        qtl[1] = *(const uint32_t*)(ql + gb + 64 + kof);
    }

    float m0 = -1e30f, m1 = -1e30f, l0 = 0.f, l1 = 0.f;
    float oacc[9][4];
#pragma unroll
    for (int dt = 0; dt < 9; dt++)
#pragma unroll
        for (int e = 0; e < 4; e++) oacc[dt][e] = 0.f;

    const int NT = PP / 64;   // 64
    for (int kt = 0; kt < NT; kt++) {
        const int s = kt & 1;
        if (kt + 1 < NT) {
            attn_fill(sb, s ^ 1, kh, kl, vh, vl, rowbase + (kt + 1) * 64, hoff, tid);
            CP_COMMIT;
            CP_WAIT1;
        } else {
            CP_WAIT0;
        }
        __syncthreads();

        const uint32_t kBh = sb + s * ASTAGE + AOFF_KH;
        const uint32_t kBl = sb + s * ASTAGE + AOFF_KL;
        const uint32_t vBh = sb + s * ASTAGE + AOFF_VH;
        const uint32_t vBl = sb + s * ASTAGE + AOFF_VL;

        // ---- S = Q K^T ----
        float sv[8][4];
#pragma unroll
        for (int nt = 0; nt < 8; nt++)
#pragma unroll
            for (int e = 0; e < 4; e++) sv[nt][e] = 0.f;

#pragma unroll
        for (int ks = 0; ks < 4; ks++) {
#pragma unroll
            for (int nt = 0; nt < 8; nt++) {
                uint32_t off = kinv + (uint32_t)(nt * 8 * 176 + ks * 32);
                uint32_t fbh[2], fbl[2];
                ldsm2(fbh, kBh + off);
                ldsm2(fbl, kBl + off);
                mma16816(sv[nt], qfh[ks], fbh);
                mma16816(sv[nt], qfh[ks], fbl);
                mma16816(sv[nt], qfl[ks], fbh);
            }
        }
        // k8 tail (dims 64..71)
#pragma unroll
        for (int nt = 0; nt < 8; nt++) {
            uint32_t off = k1inv + (uint32_t)(nt * 8 * 176 + 128);
            uint32_t bh, bl;
            ldsm1(bh, kBh + off);
            ldsm1(bl, kBl + off);
            mma16808(sv[nt], qth, bh);
            mma16808(sv[nt], qth, bl);
            mma16808(sv[nt], qtl, bh);
        }

        // ---- online softmax ----
        float mx0 = -1e30f, mx1 = -1e30f;
#pragma unroll
        for (int nt = 0; nt < 8; nt++) {
            mx0 = fmaxf(mx0, fmaxf(sv[nt][0], sv[nt][1]));
            mx1 = fmaxf(mx1, fmaxf(sv[nt][2], sv[nt][3]));
        }
        mx0 = fmaxf(mx0, __shfl_xor_sync(0xffffffffu, mx0, 1));
        mx0 = fmaxf(mx0, __shfl_xor_sync(0xffffffffu, mx0, 2));
        mx1 = fmaxf(mx1, __shfl_xor_sync(0xffffffffu, mx1, 1));
        mx1 = fmaxf(mx1, __shfl_xor_sync(0xffffffffu, mx1, 2));
        float nm0 = fmaxf(m0, mx0), nm1 = fmaxf(m1, mx1);
        float a0 = __expf(m0 - nm0), a1 = __expf(m1 - nm1);
        m0 = nm0; m1 = nm1;
        float rs0 = 0.f, rs1 = 0.f;
#pragma unroll
        for (int nt = 0; nt < 8; nt++) {
            sv[nt][0] = __expf(sv[nt][0] - nm0);
            sv[nt][1] = __expf(sv[nt][1] - nm0);
            sv[nt][2] = __expf(sv[nt][2] - nm1);
            sv[nt][3] = __expf(sv[nt][3] - nm1);
            rs0 += sv[nt][0] + sv[nt][1];
            rs1 += sv[nt][2] + sv[nt][3];
        }
        rs0 += __shfl_xor_sync(0xffffffffu, rs0, 1);
        rs0 += __shfl_xor_sync(0xffffffffu, rs0, 2);
        rs1 += __shfl_xor_sync(0xffffffffu, rs1, 1);
        rs1 += __shfl_xor_sync(0xffffffffu, rs1, 2);
        l0 = l0 * a0 + rs0;
        l1 = l1 * a1 + rs1;
#pragma unroll
        for (int dt = 0; dt < 9; dt++) {
            oacc[dt][0] *= a0; oacc[dt][1] *= a0;
            oacc[dt][2] *= a1; oacc[dt][3] *= a1;
        }

        // ---- O += P V ----
#pragma unroll
        for (int pk = 0; pk < 4; pk++) {
            uint32_t aph[4], apl[4];
            split2(sv[2 * pk][0],     sv[2 * pk][1],     aph[0], apl[0]);
            split2(sv[2 * pk][2],     sv[2 * pk][3],     aph[1], apl[1]);
            split2(sv[2 * pk + 1][0], sv[2 * pk + 1][1], aph[2], apl[2]);
            split2(sv[2 * pk + 1][2], sv[2 * pk + 1][3], aph[3], apl[3]);
            const uint32_t rowoff = (uint32_t)(pk * 16 * 144);
#pragma unroll
            for (int dtp = 0; dtp < 4; dtp++) {
                uint32_t off = vinv + rowoff + (uint32_t)(dtp * 32);
                uint32_t fh[4], fl[4];
                ldsm4t(fh, vBh + off);
                ldsm4t(fl, vBl + off);
                mma16816(oacc[2 * dtp],     aph, fh);
                mma16816(oacc[2 * dtp],     aph, fl);
                mma16816(oacc[2 * dtp],     apl, fh);
                mma16816(oacc[2 * dtp + 1], aph, fh + 2);
                mma16816(oacc[2 * dtp + 1], aph, fl + 2);
                mma16816(oacc[2 * dtp + 1], apl, fh + 2);
            }
            {   // dt = 8 (dims 64..71)
                uint32_t off = v2inv + rowoff + 128;
                uint32_t fh2[2], fl2[2];
                ldsm2t(fh2, vBh + off);
                ldsm2t(fl2, vBl + off);
                mma16816(oacc[8], aph, fh2);
                mma16816(oacc[8], aph, fl2);
                mma16816(oacc[8], apl, fh2);
            }
        }
        __syncthreads();
    }

    // ---- epilogue: write o directly as bf16 hi/lo ----
    float il0 = 1.0f / l0, il1 = 1.0f / l1;
    int ra = q0 + wid * 16 + (lane >> 2);
    size_t ga = (rowbase + ra) * HID + hoff + (lane & 3) * 2;
    size_t gb = ga + (size_t)8 * HID;
#pragma unroll
    for (int dt = 0; dt < 9; dt++) {
        uint32_t hw, lw;
        split2(oacc[dt][0] * il0, oacc[dt][1] * il0, hw, lw);
        *(uint32_t*)(oh + ga + dt * 8) = hw;
        *(uint32_t*)(ol + ga + dt * 8) = lw;
        split2(oacc[dt][2] * il1, oacc[dt][3] * il1, hw, lw);
        *(uint32_t*)(oh + gb + dt * 8) = hw;
        *(uint32_t*)(ol + gb + dt * 8) = lw;
    }
}

// ---------------------------------- launch ----------------------------------
extern "C" void kernel_launch(void* const* d_in, const int* in_sizes, int n_in,
                              void* d_out, int out_size)
{
    const float* hidden = (const float*)d_in[0];
    const float* cosb   = (const float*)d_in[1];
    const float* sinb   = (const float*)d_in[2];
    const float* Wq     = (const float*)d_in[3];
    const float* Wk     = (const float*)d_in[4];
    const float* Wv     = (const float*)d_in[5];
    const float* Wo     = (const float*)d_in[6];
    const float* qw     = (const float*)d_in[7];
    const float* kw     = (const float*)d_in[8];
    float* out = (float*)d_out;

    float *q, *k, *v;
    __nv_bfloat16 *hh, *hl, *qh, *ql, *kh, *kl, *vh, *vl;
    __nv_bfloat16 *wqh, *wql, *wkh, *wkl, *wvh, *wvl, *woh, *wol;
    cudaGetSymbolAddress((void**)&q, g_q);
    cudaGetSymbolAddress((void**)&k, g_k);
    cudaGetSymbolAddress((void**)&v, g_v);
    cudaGetSymbolAddress((void**)&hh, g_hh);
    cudaGetSymbolAddress((void**)&hl, g_hl);
    cudaGetSymbolAddress((void**)&qh, g_qh);
    cudaGetSymbolAddress((void**)&ql, g_ql);
    cudaGetSymbolAddress((void**)&kh, g_kh);
    cudaGetSymbolAddress((void**)&kl, g_kl);
    cudaGetSymbolAddress((void**)&vh, g_vh);
    cudaGetSymbolAddress((void**)&vl, g_vl);
    cudaGetSymbolAddress((void**)&wqh, g_wqh);
    cudaGetSymbolAddress((void**)&wql, g_wql);
    cudaGetSymbolAddress((void**)&wkh, g_wkh);
    cudaGetSymbolAddress((void**)&wkl, g_wkl);
    cudaGetSymbolAddress((void**)&wvh, g_wvh);
    cudaGetSymbolAddress((void**)&wvl, g_wvl);
    cudaGetSymbolAddress((void**)&woh, g_woh);
    cudaGetSymbolAddress((void**)&wol, g_wol);

    cudaFuncSetAttribute(mma_gemm_qkv, cudaFuncAttributeMaxDynamicSharedMemorySize,
                         GEMM_SMEM);
    cudaFuncSetAttribute(mma_gemm_out, cudaFuncAttributeMaxDynamicSharedMemorySize,
                         GEMM_SMEM);
    cudaFuncSetAttribute(attn_mma, cudaFuncAttributeMaxDynamicSharedMemorySize,
                         ATTN_SMEM);

    const int NH4 = (MTOT * HID) / 4;
    const int NW4 = (HID * HID) / 4;

    split_kernel<<<NH4 / 256, 256>>>(hidden, hh, hl, NH4);
    split_kernel<<<NW4 / 256, 256>>>(Wq, wqh, wql, NW4);
    split_kernel<<<NW4 / 256, 256>>>(Wk, wkh, wkl, NW4);
    split_kernel<<<NW4 / 256, 256>>>(Wv, wvh, wvl, NW4);
    split_kernel<<<NW4 / 256, 256>>>(Wo, woh, wol, NW4);

    dim3 qkvgrid(HID / 128, MTOT / 128, 3);
    mma_gemm_qkv<<<qkvgrid, 256, GEMM_SMEM>>>(hh, hl, wqh, wql, wkh, wkl,
                                              wvh, wvl, q, k, v);

    norm_rope_split<<<(BB * PP * NH) / 8, 256>>>(q, k, v, cosb, sinb, qw, kw,
                                                 qh, ql, kh, kl, vh, vl);

    dim3 agrid(PP / 128, NH, BB);
    attn_mma<<<agrid, 256, ATTN_SMEM>>>(qh, ql, kh, kl, vh, vl, hh, hl);

    dim3 ogrid(HID / 128, MTOT / 128);
    mma_gemm_out<<<ogrid, 256, GEMM_SMEM>>>(hh, hl, woh, wol, out);
}

// round 6
// speedup vs baseline: 4.3767x; 1.1699x over previous
#include <cuda_runtime.h>
#include <cuda_fp16.h>
#include <math.h>
#include <stdint.h>

#define BB 2
#define PP 4096
#define HID 1152
#define NH 16
#define HD 72
#define MTOT (BB*PP)            // 8192

// ---------------- scratch (device globals; no allocations allowed) ----------
__device__ float g_q[(size_t)MTOT * HID];
__device__ float g_k[(size_t)MTOT * HID];
__device__ float g_v[(size_t)MTOT * HID];
__device__ __half g_hh[(size_t)MTOT * HID];   // hidden hi (reused for o hi)
__device__ __half g_hl[(size_t)MTOT * HID];   // hidden lo
__device__ __half g_qh[(size_t)MTOT * HID];
__device__ __half g_ql[(size_t)MTOT * HID];
__device__ __half g_kh[(size_t)MTOT * HID];
__device__ __half g_kl[(size_t)MTOT * HID];
__device__ __half g_vh[(size_t)MTOT * HID];
__device__ __half g_vl[(size_t)MTOT * HID];
__device__ __half g_wqh[(size_t)HID * HID];
__device__ __half g_wql[(size_t)HID * HID];
__device__ __half g_wkh[(size_t)HID * HID];
__device__ __half g_wkl[(size_t)HID * HID];
__device__ __half g_wvh[(size_t)HID * HID];
__device__ __half g_wvl[(size_t)HID * HID];
__device__ __half g_woh[(size_t)HID * HID];
__device__ __half g_wol[(size_t)HID * HID];

// ---------------- low-level helpers -----------------------------------------
__device__ __forceinline__ uint32_t smem_u32(const void* p) {
    uint32_t a;
    asm("{ .reg .u64 t; cvta.to.shared.u64 t, %1; cvt.u32.u64 %0, t; }"
        : "=r"(a) : "l"(p));
    return a;
}

__device__ __forceinline__ void mma16816(float* c, const uint32_t* a, const uint32_t* b) {
    asm volatile(
        "mma.sync.aligned.m16n8k16.row.col.f32.f16.f16.f32 "
        "{%0,%1,%2,%3}, {%4,%5,%6,%7}, {%8,%9}, {%0,%1,%2,%3};"
        : "+f"(c[0]), "+f"(c[1]), "+f"(c[2]), "+f"(c[3])
        : "r"(a[0]), "r"(a[1]), "r"(a[2]), "r"(a[3]), "r"(b[0]), "r"(b[1]));
}

__device__ __forceinline__ void mma16808(float* c, const uint32_t* a, uint32_t b) {
    asm volatile(
        "mma.sync.aligned.m16n8k8.row.col.f32.f16.f16.f32 "
        "{%0,%1,%2,%3}, {%4,%5}, {%6}, {%0,%1,%2,%3};"
        : "+f"(c[0]), "+f"(c[1]), "+f"(c[2]), "+f"(c[3])
        : "r"(a[0]), "r"(a[1]), "r"(b));
}

__device__ __forceinline__ void split2(float x0, float x1, uint32_t& h, uint32_t& l) {
    __half h0 = __float2half_rn(x0);
    __half h1 = __float2half_rn(x1);
    __half2 hv; hv.x = h0; hv.y = h1;
    __half2 lv = __floats2half2_rn(x0 - __half2float(h0), x1 - __half2float(h1));
    h = *(uint32_t*)&hv;
    l = *(uint32_t*)&lv;
}

__device__ __forceinline__ uint32_t pack_h2(float x0, float x1) {
    __half2 hv = __floats2half2_rn(x0, x1);
    return *(uint32_t*)&hv;
}

__device__ __forceinline__ uint32_t lds32a(uint32_t a) {
    uint32_t v; asm volatile("ld.shared.b32 %0, [%1];" : "=r"(v) : "r"(a)); return v;
}

__device__ __forceinline__ void ldsm1(uint32_t& r, uint32_t a) {
    asm volatile("ldmatrix.sync.aligned.m8n8.x1.shared.b16 {%0}, [%1];"
                 : "=r"(r) : "r"(a));
}
__device__ __forceinline__ void ldsm2(uint32_t* r, uint32_t a) {
    asm volatile("ldmatrix.sync.aligned.m8n8.x2.shared.b16 {%0,%1}, [%2];"
                 : "=r"(r[0]), "=r"(r[1]) : "r"(a));
}
__device__ __forceinline__ void ldsm2t(uint32_t* r, uint32_t a) {
    asm volatile("ldmatrix.sync.aligned.m8n8.x2.trans.shared.b16 {%0,%1}, [%2];"
                 : "=r"(r[0]), "=r"(r[1]) : "r"(a));
}
__device__ __forceinline__ void ldsm4t(uint32_t* r, uint32_t a) {
    asm volatile("ldmatrix.sync.aligned.m8n8.x4.trans.shared.b16 {%0,%1,%2,%3}, [%4];"
                 : "=r"(r[0]), "=r"(r[1]), "=r"(r[2]), "=r"(r[3]) : "r"(a));
}

__device__ __forceinline__ void cpa16(uint32_t dst, const void* src) {
    asm volatile("cp.async.cg.shared.global [%0], [%1], 16;" :: "r"(dst), "l"(src));
}
#define CP_COMMIT asm volatile("cp.async.commit_group;" ::: "memory")
#define CP_WAIT0 asm volatile("cp.async.wait_group 0;" ::: "memory")
#define CP_WAIT1 asm volatile("cp.async.wait_group 1;" ::: "memory")

// ---------------- split: fp32 -> fp16 hi/lo ----------------------------------
__global__ void split_kernel(const float* __restrict__ s, __half* __restrict__ h,
                             __half* __restrict__ l, int n4)
{
    int i = blockIdx.x * blockDim.x + threadIdx.x;
    if (i >= n4) return;
    float4 v = ((const float4*)s)[i];
    uint32_t h0, l0, h1, l1;
    split2(v.x, v.y, h0, l0);
    split2(v.z, v.w, h1, l1);
    ((uint32_t*)h)[i * 2]     = h0;
    ((uint32_t*)h)[i * 2 + 1] = h1;
    ((uint32_t*)l)[i * 2]     = l0;
    ((uint32_t*)l)[i * 2 + 1] = l1;
}

// ============== pipelined MMA GEMM: C = A @ W, fp16 split, PRODS=3|2 ========
// PRODS==3: C = Ah*Bh + Ah*Bl + Al*Bh.  PRODS==2: C = Ah*Bh + Ah*Bl (A-lo unused).
#define GOFF_AH 0
#define GOFF_AL 10240
#define GOFF_BH 20480
#define GOFF_BL 29184
#define GSTAGE  37888
#define GEMM_SMEM (2*GSTAGE)

template<int PRODS>
__device__ __forceinline__ void gemm_fill(uint32_t sb, int s,
    const __half* __restrict__ aH, const __half* __restrict__ aL,
    const __half* __restrict__ bH, const __half* __restrict__ bL,
    int m0, int n0, int k0, int tid)
{
    uint32_t st = sb + s * GSTAGE;
#pragma unroll
    for (int rep = 0; rep < 2; rep++) {
        int i = tid + rep * 256;
        {
            int r = i >> 2, c = i & 3;
            uint32_t off = (uint32_t)(r * 80 + c * 16);
            size_t g = (size_t)(m0 + r) * HID + k0 + c * 8;
            cpa16(st + GOFF_AH + off, aH + g);
            if (PRODS == 3) cpa16(st + GOFF_AL + off, aL + g);
        }
        {
            int r = i >> 4, c = i & 15;
            uint32_t off = (uint32_t)(r * 272 + c * 16);
            size_t g = (size_t)(k0 + r) * HID + n0 + c * 8;
            cpa16(st + GOFF_BH + off, bH + g);
            cpa16(st + GOFF_BL + off, bL + g);
        }
    }
}

template<int PRODS>
__device__ __forceinline__ void mma_gemm_body(
    const __half* __restrict__ aH, const __half* __restrict__ aL,
    const __half* __restrict__ bH, const __half* __restrict__ bL,
    float* __restrict__ C, int m0, int n0)
{
    extern __shared__ char smem[];
    const uint32_t sb = smem_u32(smem);
    const int tid = threadIdx.x;
    const int lane = tid & 31;
    const int wid = tid >> 5;
    const int wm = wid & 3;
    const int wn = wid >> 2;

    float c[2][8][4];
#pragma unroll
    for (int mt = 0; mt < 2; mt++)
#pragma unroll
        for (int nt = 0; nt < 8; nt++)
#pragma unroll
            for (int e = 0; e < 4; e++) c[mt][nt][e] = 0.f;

    gemm_fill<PRODS>(sb, 0, aH, aL, bH, bL, m0, n0, 0, tid);
    CP_COMMIT;

    const int NCH = HID / 32;   // 36
    for (int ch = 0; ch < NCH; ch++) {
        const int s = ch & 1;
        if (ch + 1 < NCH) {
            gemm_fill<PRODS>(sb, s ^ 1, aH, aL, bH, bL, m0, n0, (ch + 1) * 32, tid);
            CP_COMMIT;
            CP_WAIT1;
        } else {
            CP_WAIT0;
        }
        __syncthreads();

        const uint32_t aBh = sb + s * GSTAGE + GOFF_AH;
        const uint32_t aBl = sb + s * GSTAGE + GOFF_AL;
        const uint32_t bBh = sb + s * GSTAGE + GOFF_BH;
        const uint32_t bBl = sb + s * GSTAGE + GOFF_BL;

#pragma unroll
        for (int ks = 0; ks < 2; ks++) {
            const int kk = ks * 16 + (lane & 3) * 2;
            uint32_t fah[2][4], fal[2][4];
#pragma unroll
            for (int mt = 0; mt < 2; mt++) {
                int r0 = wm * 32 + mt * 16 + (lane >> 2);
                uint32_t o0 = (uint32_t)(r0 * 40 + kk) * 2;
                uint32_t o1 = o0 + 8 * 80;
                fah[mt][0] = lds32a(aBh + o0);      fah[mt][1] = lds32a(aBh + o1);
                fah[mt][2] = lds32a(aBh + o0 + 16); fah[mt][3] = lds32a(aBh + o1 + 16);
                if (PRODS == 3) {
                    fal[mt][0] = lds32a(aBl + o0);      fal[mt][1] = lds32a(aBl + o1);
                    fal[mt][2] = lds32a(aBl + o0 + 16); fal[mt][3] = lds32a(aBl + o1 + 16);
                }
            }
#pragma unroll
            for (int nt = 0; nt < 8; nt++) {
                uint32_t bo = (uint32_t)((ks * 16 + (lane & 15)) * 136
                                         + wn * 64 + nt * 8) * 2;
                uint32_t fbh[2], fbl[2];
                ldsm2t(fbh, bBh + bo);
                ldsm2t(fbl, bBl + bo);
#pragma unroll
                for (int mt = 0; mt < 2; mt++) {
                    mma16816(c[mt][nt], fah[mt], fbh);
                    mma16816(c[mt][nt], fah[mt], fbl);
                    if (PRODS == 3) mma16816(c[mt][nt], fal[mt], fbh);
                }
            }
        }
        __syncthreads();
    }

#pragma unroll
    for (int mt = 0; mt < 2; mt++) {
#pragma unroll
        for (int nt = 0; nt < 8; nt++) {
            int row = m0 + wm * 32 + mt * 16 + (lane >> 2);
            int col = n0 + wn * 64 + nt * 8 + (lane & 3) * 2;
            *(float2*)(C + (size_t)row * HID + col) =
                make_float2(c[mt][nt][0], c[mt][nt][1]);
            *(float2*)(C + (size_t)(row + 8) * HID + col) =
                make_float2(c[mt][nt][2], c[mt][nt][3]);
        }
    }
}

__global__ __launch_bounds__(256, 2)
void mma_gemm_qk(const __half* __restrict__ aH, const __half* __restrict__ aL,
                 const __half* __restrict__ qWh, const __half* __restrict__ qWl,
                 const __half* __restrict__ kWh, const __half* __restrict__ kWl,
                 float* __restrict__ q, float* __restrict__ k)
{
    const __half* wH = (blockIdx.z == 0) ? qWh : kWh;
    const __half* wL = (blockIdx.z == 0) ? qWl : kWl;
    float* C = (blockIdx.z == 0) ? q : k;
    mma_gemm_body<3>(aH, aL, wH, wL, C, blockIdx.y * 128, blockIdx.x * 128);
}

__global__ __launch_bounds__(256, 2)
void mma_gemm_2p(const __half* __restrict__ aH,
                 const __half* __restrict__ wH, const __half* __restrict__ wL,
                 float* __restrict__ C)
{
    mma_gemm_body<2>(aH, aH, wH, wL, C, blockIdx.y * 128, blockIdx.x * 128);
}

// ------------- fused RMSNorm (+weight) + 2D RoPE + fp16 hi/lo split ---------
__global__ void norm_rope_split(const float* __restrict__ q, const float* __restrict__ k,
                                const float* __restrict__ v,
                                const float* __restrict__ cosb,
                                const float* __restrict__ sinb,
                                const float* __restrict__ qw,
                                const float* __restrict__ kw,
                                __half* __restrict__ qh, __half* __restrict__ ql,
                                __half* __restrict__ kh, __half* __restrict__ kl,
                                __half* __restrict__ vh, __half* __restrict__ vl)
{
    __shared__ float sm[8][HD];
    int warp = threadIdx.x >> 5;
    int lane = threadIdx.x & 31;
    int gid = blockIdx.x * 8 + warp;
    int bp = gid >> 4;
    int h  = gid & 15;
    size_t base  = (size_t)bp * HID + (size_t)h * HD;
    size_t cbase = (size_t)bp * HD;

    float c0 = cosb[cbase + lane],      s0 = sinb[cbase + lane];
    float c1 = cosb[cbase + 32 + lane], s1 = sinb[cbase + 32 + lane];
    float c2 = 0.f, s2 = 0.f;
    if (lane < 8) { c2 = cosb[cbase + 64 + lane]; s2 = sinb[cbase + 64 + lane]; }

#pragma unroll
    for (int t = 0; t < 2; t++) {
        const float* buf = (t == 0) ? q : k;
        const float* w = (t == 0) ? qw : kw;
        __half* oh = (t == 0) ? qh : kh;
        __half* ol = (t == 0) ? ql : kl;
        float x0 = buf[base + lane];
        float x1 = buf[base + 32 + lane];
        float x2 = (lane < 8) ? buf[base + 64 + lane] : 0.f;
        float ss = x0 * x0 + x1 * x1 + x2 * x2;
#pragma unroll
        for (int m = 16; m; m >>= 1) ss += __shfl_xor_sync(0xffffffffu, ss, m);
        float r = rsqrtf(ss * (1.0f / 72.0f) + 1e-6f);
        sm[warp][lane]      = x0 * r * w[lane];
        sm[warp][lane + 32] = x1 * r * w[lane + 32];
        if (lane < 8) sm[warp][lane + 64] = x2 * r * w[lane + 64];
        __syncwarp();
        {
            int d = lane;
            int jj = (d < 36) ? d : d - 36;
            float rh = (jj < 18) ? -sm[warp][d + 18] : sm[warp][d - 18];
            float out = sm[warp][d] * c0 + rh * s0;
            __half hh = __float2half_rn(out);
            oh[base + d] = hh;
            ol[base + d] = __float2half_rn(out - __half2float(hh));
        }
        {
            int d = lane + 32;
            int jj = (d < 36) ? d : d - 36;
            float rh = (jj < 18) ? -sm[warp][d + 18] : sm[warp][d - 18];
            float out = sm[warp][d] * c1 + rh * s1;
            __half hh = __float2half_rn(out);
            oh[base + d] = hh;
            ol[base + d] = __float2half_rn(out - __half2float(hh));
        }
        if (lane < 8) {
            int d = lane + 64;
            int jj = d - 36;
            float rh = (jj < 18) ? -sm[warp][d + 18] : sm[warp][d - 18];
            float out = sm[warp][d] * c2 + rh * s2;
            __half hh = __float2half_rn(out);
            oh[base + d] = hh;
            ol[base + d] = __float2half_rn(out - __half2float(hh));
        }
        __syncwarp();
    }
    {
        float x0 = v[base + lane];
        float x1 = v[base + 32 + lane];
        float x2 = (lane < 8) ? v[base + 64 + lane] : 0.f;
        float ss = x0 * x0 + x1 * x1 + x2 * x2;
#pragma unroll
        for (int m = 16; m; m >>= 1) ss += __shfl_xor_sync(0xffffffffu, ss, m);
        float r = rsqrtf(ss * (1.0f / 72.0f) + 1e-6f);
#pragma unroll
        for (int part = 0; part < 3; part++) {
            int d = lane + part * 32;
            if (d < HD) {
                float out = ((part == 0) ? x0 : (part == 1) ? x1 : x2) * r;
                __half hh = __float2half_rn(out);
                vh[base + d] = hh;
                vl[base + d] = __float2half_rn(out - __half2float(hh));
            }
        }
    }
}

// ---------------- pipelined flash attention (mma.sync fp16) -----------------
// QK: fp16x3 (q hi/lo x k hi/lo, drop lo*lo). PV: P-hi x V hi/lo (2 products).
// K smem [64][88] hi/lo, V smem [64][72] hi/lo, 2-stage cp.async.
#define AOFF_KH 0
#define AOFF_KL 11264
#define AOFF_VH 22528
#define AOFF_VL 31744
#define ASTAGE  40960
#define ATTN_SMEM (2*ASTAGE)

__device__ __forceinline__ void attn_fill(uint32_t sb, int s,
    const __half* __restrict__ kh, const __half* __restrict__ kl,
    const __half* __restrict__ vh, const __half* __restrict__ vl,
    size_t kb, size_t hoff, int tid)
{
    uint32_t st = sb + s * ASTAGE;
    for (int i = tid; i < 576; i += 256) {
        int r = i / 9, c = i - r * 9;
        size_t g = (kb + r) * HID + hoff + c * 8;
        uint32_t ko = (uint32_t)(r * 176 + c * 16);
        uint32_t vo = (uint32_t)(r * 144 + c * 16);
        cpa16(st + AOFF_KH + ko, kh + g);
        cpa16(st + AOFF_KL + ko, kl + g);
        cpa16(st + AOFF_VH + vo, vh + g);
        cpa16(st + AOFF_VL + vo, vl + g);
    }
}

__global__ __launch_bounds__(256, 2)
void attn_mma(const __half* __restrict__ qh, const __half* __restrict__ ql,
              const __half* __restrict__ kh, const __half* __restrict__ kl,
              const __half* __restrict__ vh, const __half* __restrict__ vl,
              __half* __restrict__ oh)
{
    extern __shared__ char smem[];
    const uint32_t sb = smem_u32(smem);
    const int tid = threadIdx.x;
    const int lane = tid & 31;
    const int wid = tid >> 5;
    const int b = blockIdx.z, h = blockIdx.y;
    const int q0 = blockIdx.x * 128;
    const size_t rowbase = (size_t)b * PP;
    const size_t hoff = (size_t)h * HD;

    attn_fill(sb, 0, kh, kl, vh, vl, rowbase, hoff, tid);
    CP_COMMIT;

    const uint32_t kinv  = (uint32_t)((lane & 7) * 176 + ((lane >> 3) & 1) * 16);
    const uint32_t k1inv = (uint32_t)((lane & 7) * 176);
    const uint32_t vinv  = (uint32_t)((lane & 15) * 144 + (lane >> 4) * 16);
    const uint32_t v2inv = (uint32_t)((lane & 15) * 144);

    // ---- Q fragments, register resident (hi & lo), k16 x4 + k8 tail ----
    uint32_t qfh[4][4], qfl[4][4], qth[2], qtl[2];
    {
        int ra = q0 + wid * 16 + (lane >> 2);
        const size_t ga = (rowbase + ra) * HID + hoff;
        const size_t gb = ga + (size_t)8 * HID;
        const int kof = (lane & 3) * 2;
#pragma unroll
        for (int ks = 0; ks < 4; ks++) {
            int kk = ks * 16 + kof;
            qfh[ks][0] = *(const uint32_t*)(qh + ga + kk);
            qfh[ks][1] = *(const uint32_t*)(qh + gb + kk);
            qfh[ks][2] = *(const uint32_t*)(qh + ga + kk + 8);
            qfh[ks][3] = *(const uint32_t*)(qh + gb + kk + 8);
            qfl[ks][0] = *(const uint32_t*)(ql + ga + kk);
            qfl[ks][1] = *(const uint32_t*)(ql + gb + kk);
            qfl[ks][2] = *(const uint32_t*)(ql + ga + kk + 8);
            qfl[ks][3] = *(const uint32_t*)(ql + gb + kk + 8);
        }
        qth[0] = *(const uint32_t*)(qh + ga + 64 + kof);
        qth[1] = *(const uint32_t*)(qh + gb + 64 + kof);
        qtl[0] = *(const uint32_t*)(ql + ga + 64 + kof);
        qtl[1] = *(const uint32_t*)(ql + gb + 64 + kof);
    }

    float m0 = -1e30f, m1 = -1e30f, l0 = 0.f, l1 = 0.f;
    float oacc[9][4];
#pragma unroll
    for (int dt = 0; dt < 9; dt++)
#pragma unroll
        for (int e = 0; e < 4; e++) oacc[dt][e] = 0.f;

    const int NT = PP / 64;   // 64
    for (int kt = 0; kt < NT; kt++) {
        const int s = kt & 1;
        if (kt + 1 < NT) {
            attn_fill(sb, s ^ 1, kh, kl, vh, vl, rowbase + (kt + 1) * 64, hoff, tid);
            CP_COMMIT;
            CP_WAIT1;
        } else {
            CP_WAIT0;
        }
        __syncthreads();

        const uint32_t kBh = sb + s * ASTAGE + AOFF_KH;
        const uint32_t kBl = sb + s * ASTAGE + AOFF_KL;
        const uint32_t vBh = sb + s * ASTAGE + AOFF_VH;
        const uint32_t vBl = sb + s * ASTAGE + AOFF_VL;

        // ---- S = Q K^T (3 products) ----
        float sv[8][4];
#pragma unroll
        for (int nt = 0; nt < 8; nt++)
#pragma unroll
            for (int e = 0; e < 4; e++) sv[nt][e] = 0.f;

#pragma unroll
        for (int ks = 0; ks < 4; ks++) {
#pragma unroll
            for (int nt = 0; nt < 8; nt++) {
                uint32_t off = kinv + (uint32_t)(nt * 8 * 176 + ks * 32);
                uint32_t fbh[2], fbl[2];
                ldsm2(fbh, kBh + off);
                ldsm2(fbl, kBl + off);
                mma16816(sv[nt], qfh[ks], fbh);
                mma16816(sv[nt], qfh[ks], fbl);
                mma16816(sv[nt], qfl[ks], fbh);
            }
        }
#pragma unroll
        for (int nt = 0; nt < 8; nt++) {
            uint32_t off = k1inv + (uint32_t)(nt * 8 * 176 + 128);
            uint32_t bh, bl;
            ldsm1(bh, kBh + off);
            ldsm1(bl, kBl + off);
            mma16808(sv[nt], qth, bh);
            mma16808(sv[nt], qth, bl);
            mma16808(sv[nt], qtl, bh);
        }

        // ---- online softmax ----
        float mx0 = -1e30f, mx1 = -1e30f;
#pragma unroll
        for (int nt = 0; nt < 8; nt++) {
            mx0 = fmaxf(mx0, fmaxf(sv[nt][0], sv[nt][1]));
            mx1 = fmaxf(mx1, fmaxf(sv[nt][2], sv[nt][3]));
        }
        mx0 = fmaxf(mx0, __shfl_xor_sync(0xffffffffu, mx0, 1));
        mx0 = fmaxf(mx0, __shfl_xor_sync(0xffffffffu, mx0, 2));
        mx1 = fmaxf(mx1, __shfl_xor_sync(0xffffffffu, mx1, 1));
        mx1 = fmaxf(mx1, __shfl_xor_sync(0xffffffffu, mx1, 2));
        float nm0 = fmaxf(m0, mx0), nm1 = fmaxf(m1, mx1);
        float a0 = __expf(m0 - nm0), a1 = __expf(m1 - nm1);
        m0 = nm0; m1 = nm1;
        float rs0 = 0.f, rs1 = 0.f;
#pragma unroll
        for (int nt = 0; nt < 8; nt++) {
            sv[nt][0] = __expf(sv[nt][0] - nm0);
            sv[nt][1] = __expf(sv[nt][1] - nm0);
            sv[nt][2] = __expf(sv[nt][2] - nm1);
            sv[nt][3] = __expf(sv[nt][3] - nm1);
            rs0 += sv[nt][0] + sv[nt][1];
            rs1 += sv[nt][2] + sv[nt][3];
        }
        rs0 += __shfl_xor_sync(0xffffffffu, rs0, 1);
        rs0 += __shfl_xor_sync(0xffffffffu, rs0, 2);
        rs1 += __shfl_xor_sync(0xffffffffu, rs1, 1);
        rs1 += __shfl_xor_sync(0xffffffffu, rs1, 2);
        l0 = l0 * a0 + rs0;
        l1 = l1 * a1 + rs1;
#pragma unroll
        for (int dt = 0; dt < 9; dt++) {
            oacc[dt][0] *= a0; oacc[dt][1] *= a0;
            oacc[dt][2] *= a1; oacc[dt][3] *= a1;
        }

        // ---- O += P_hi V (2 products: P*Vhi + P*Vlo) ----
#pragma unroll
        for (int pk = 0; pk < 4; pk++) {
            uint32_t aph[4];
            aph[0] = pack_h2(sv[2 * pk][0],     sv[2 * pk][1]);
            aph[1] = pack_h2(sv[2 * pk][2],     sv[2 * pk][3]);
            aph[2] = pack_h2(sv[2 * pk + 1][0], sv[2 * pk + 1][1]);
            aph[3] = pack_h2(sv[2 * pk + 1][2], sv[2 * pk + 1][3]);
            const uint32_t rowoff = (uint32_t)(pk * 16 * 144);
#pragma unroll
            for (int dtp = 0; dtp < 4; dtp++) {
                uint32_t off = vinv + rowoff + (uint32_t)(dtp * 32);
                uint32_t fh[4], fl[4];
                ldsm4t(fh, vBh + off);
                ldsm4t(fl, vBl + off);
                mma16816(oacc[2 * dtp],     aph, fh);
                mma16816(oacc[2 * dtp],     aph, fl);
                mma16816(oacc[2 * dtp + 1], aph, fh + 2);
                mma16816(oacc[2 * dtp + 1], aph, fl + 2);
            }
            {   // dt = 8 (dims 64..71)
                uint32_t off = v2inv + rowoff + 128;
                uint32_t fh2[2], fl2[2];
                ldsm2t(fh2, vBh + off);
                ldsm2t(fl2, vBl + off);
                mma16816(oacc[8], aph, fh2);
                mma16816(oacc[8], aph, fl2);
            }
        }
        __syncthreads();
    }

    // ---- epilogue: write o-hi only (out-proj uses 2-product form) ----
    float il0 = 1.0f / l0, il1 = 1.0f / l1;
    int ra = q0 + wid * 16 + (lane >> 2);
    size_t ga = (rowbase + ra) * HID + hoff + (lane & 3) * 2;
    size_t gb = ga + (size_t)8 * HID;
#pragma unroll
    for (int dt = 0; dt < 9; dt++) {
        *(uint32_t*)(oh + ga + dt * 8) =
            pack_h2(oacc[dt][0] * il0, oacc[dt][1] * il0);
        *(uint32_t*)(oh + gb + dt * 8) =
            pack_h2(oacc[dt][2] * il1, oacc[dt][3] * il1);
    }
}

// ---------------------------------- launch ----------------------------------
extern "C" void kernel_launch(void* const* d_in, const int* in_sizes, int n_in,
                              void* d_out, int out_size)
{
    const float* hidden = (const float*)d_in[0];
    const float* cosb   = (const float*)d_in[1];
    const float* sinb   = (const float*)d_in[2];
    const float* Wq     = (const float*)d_in[3];
    const float* Wk     = (const float*)d_in[4];
    const float* Wv     = (const float*)d_in[5];
    const float* Wo     = (const float*)d_in[6];
    const float* qw     = (const float*)d_in[7];
    const float* kw     = (const float*)d_in[8];
    float* out = (float*)d_out;

    float *q, *k, *v;
    __half *hh, *hl, *qh, *ql, *kh, *kl, *vh, *vl;
    __half *wqh, *wql, *wkh, *wkl, *wvh, *wvl, *woh, *wol;
    cudaGetSymbolAddress((void**)&q, g_q);
    cudaGetSymbolAddress((void**)&k, g_k);
    cudaGetSymbolAddress((void**)&v, g_v);
    cudaGetSymbolAddress((void**)&hh, g_hh);
    cudaGetSymbolAddress((void**)&hl, g_hl);
    cudaGetSymbolAddress((void**)&qh, g_qh);
    cudaGetSymbolAddress((void**)&ql, g_ql);
    cudaGetSymbolAddress((void**)&kh, g_kh);
    cudaGetSymbolAddress((void**)&kl, g_kl);
    cudaGetSymbolAddress((void**)&vh, g_vh);
    cudaGetSymbolAddress((void**)&vl, g_vl);
    cudaGetSymbolAddress((void**)&wqh, g_wqh);
    cudaGetSymbolAddress((void**)&wql, g_wql);
    cudaGetSymbolAddress((void**)&wkh, g_wkh);
    cudaGetSymbolAddress((void**)&wkl, g_wkl);
    cudaGetSymbolAddress((void**)&wvh, g_wvh);
    cudaGetSymbolAddress((void**)&wvl, g_wvl);
    cudaGetSymbolAddress((void**)&woh, g_woh);
    cudaGetSymbolAddress((void**)&wol, g_wol);

    cudaFuncSetAttribute(mma_gemm_qk, cudaFuncAttributeMaxDynamicSharedMemorySize,
                         GEMM_SMEM);
    cudaFuncSetAttribute(mma_gemm_2p, cudaFuncAttributeMaxDynamicSharedMemorySize,
                         GEMM_SMEM);
    cudaFuncSetAttribute(attn_mma, cudaFuncAttributeMaxDynamicSharedMemorySize,
                         ATTN_SMEM);

    const int NH4 = (MTOT * HID) / 4;
    const int NW4 = (HID * HID) / 4;

    split_kernel<<<NH4 / 256, 256>>>(hidden, hh, hl, NH4);
    split_kernel<<<NW4 / 256, 256>>>(Wq, wqh, wql, NW4);
    split_kernel<<<NW4 / 256, 256>>>(Wk, wkh, wkl, NW4);
    split_kernel<<<NW4 / 256, 256>>>(Wv, wvh, wvl, NW4);
    split_kernel<<<NW4 / 256, 256>>>(Wo, woh, wol, NW4);

    dim3 qkgrid(HID / 128, MTOT / 128, 2);
    mma_gemm_qk<<<qkgrid, 256, GEMM_SMEM>>>(hh, hl, wqh, wql, wkh, wkl, q, k);

    dim3 vgrid(HID / 128, MTOT / 128);
    mma_gemm_2p<<<vgrid, 256, GEMM_SMEM>>>(hh, wvh, wvl, v);

    norm_rope_split<<<(BB * PP * NH) / 8, 256>>>(q, k, v, cosb, sinb, qw, kw,
                                                 qh, ql, kh, kl, vh, vl);

    dim3 agrid(PP / 128, NH, BB);
    attn_mma<<<agrid, 256, ATTN_SMEM>>>(qh, ql, kh, kl, vh, vl, hh);

    dim3 ogrid(HID / 128, MTOT / 128);
    mma_gemm_2p<<<ogrid, 256, GEMM_SMEM>>>(hh, woh, wol, out);
}